// round 2
// baseline (speedup 1.0000x reference)
#include <cuda_runtime.h>

#define BB 16
#define NN 4096
#define CC 64
#define NPT 1024
#define NSMP 32

// ---------------- scratch (device globals; no allocations allowed) ----------
__device__ __align__(16) float g_pre1[BB * NN * CC];   // 16 MB: per-point layer-1 pre-activation
__device__ float g_new_xyz[BB * NPT * 3];
__device__ int   g_fps[BB * NPT];
__device__ int   g_idx[BB * NPT * NSMP];

// ---------------------------------------------------------------------------
// K1: blocks [0,16): farthest point sampling (one block per batch)
//     blocks [16,..): pre1 = xyz @ W1[:3] + points @ W1[3:]  (per original point)
// ---------------------------------------------------------------------------
extern "C" __global__ void __launch_bounds__(1024)
k_fps_pre1(const float* __restrict__ xyz, const float* __restrict__ points,
           const float* __restrict__ W1, float* __restrict__ out_xyz)
{
    extern __shared__ float sm[];
    int t = threadIdx.x;

    if (blockIdx.x < BB) {
        // ---------------- FPS ----------------
        int b = blockIdx.x;
        float* sx = sm;
        float* sy = sm + NN;
        float* sz = sm + 2 * NN;
        float* swv = sm + 3 * NN;               // 32 warp best values
        int*   swi = (int*)(sm + 3 * NN + 32);  // 32 warp best indices
        float* scur = sm + 3 * NN + 64;         // current centroid xyz
        int*   sfar = (int*)(sm + 3 * NN + 68); // current farthest index

        const float* xb = xyz + (size_t)b * NN * 3;
        for (int i = t; i < NN * 3; i += 1024) {
            int n = i / 3, c = i - n * 3;
            float v = xb[i];
            ((c == 0) ? sx : (c == 1) ? sy : sz)[n] = v;
        }
        __syncthreads();

        float px[4], py[4], pz[4], dd[4];
        #pragma unroll
        for (int j = 0; j < 4; j++) {
            int p = t + j * 1024;
            px[j] = sx[p]; py[j] = sy[p]; pz[j] = sz[p];
            dd[j] = 1e10f;
        }
        if (t == 0) { scur[0] = sx[0]; scur[1] = sy[0]; scur[2] = sz[0]; sfar[0] = 0; }
        __syncthreads();

        for (int s = 0; s < NPT; s++) {
            float cx = scur[0], cy = scur[1], cz = scur[2];
            if (t == 0) g_fps[b * NPT + s] = sfar[0];

            float bestv = -1.0f; int besti = 0;
            #pragma unroll
            for (int j = 0; j < 4; j++) {
                // match XLA: square via mul, left-assoc add tree, no fma contraction
                float dx = __fadd_rn(px[j], -cx);
                float dy = __fadd_rn(py[j], -cy);
                float dz = __fadd_rn(pz[j], -cz);
                float d = __fadd_rn(__fadd_rn(__fmul_rn(dx, dx), __fmul_rn(dy, dy)),
                                    __fmul_rn(dz, dz));
                dd[j] = fminf(dd[j], d);
                if (dd[j] > bestv) { bestv = dd[j]; besti = t + j * 1024; }
            }
            // warp argmax (first-occurrence tie break: smaller index)
            #pragma unroll
            for (int off = 16; off > 0; off >>= 1) {
                float ov = __shfl_down_sync(0xffffffffu, bestv, off);
                int   oi = __shfl_down_sync(0xffffffffu, besti, off);
                if (ov > bestv || (ov == bestv && oi < besti)) { bestv = ov; besti = oi; }
            }
            if ((t & 31) == 0) { swv[t >> 5] = bestv; swi[t >> 5] = besti; }
            __syncthreads();
            if (t < 32) {
                bestv = swv[t]; besti = swi[t];
                #pragma unroll
                for (int off = 16; off > 0; off >>= 1) {
                    float ov = __shfl_down_sync(0xffffffffu, bestv, off);
                    int   oi = __shfl_down_sync(0xffffffffu, besti, off);
                    if (ov > bestv || (ov == bestv && oi < besti)) { bestv = ov; besti = oi; }
                }
                if (t == 0) {
                    sfar[0] = besti;
                    scur[0] = sx[besti]; scur[1] = sy[besti]; scur[2] = sz[besti];
                }
            }
            __syncthreads();
        }

        // gather new_xyz (t = 0..1023 == centroid id)
        {
            int fi = g_fps[b * NPT + t];
            float nx = sx[fi], ny = sy[fi], nz = sz[fi];
            int o = (b * NPT + t) * 3;
            g_new_xyz[o] = nx; g_new_xyz[o + 1] = ny; g_new_xyz[o + 2] = nz;
            out_xyz[o] = nx; out_xyz[o + 1] = ny; out_xyz[o + 2] = nz;
        }
    } else {
        // ---------------- pre1 ----------------
        float* W1s = sm; // 67*64 floats
        for (int i = t; i < 67 * 64; i += 1024) W1s[i] = W1[i];
        __syncthreads();
        int nb = gridDim.x - BB;
        const int total = BB * NN * CC;
        for (int e = (blockIdx.x - BB) * 1024 + t; e < total; e += nb * 1024) {
            int r = e >> 6;       // global point row (b*N + n)
            int d = e & 63;       // output channel
            const float* xr = xyz + (size_t)r * 3;
            float acc = fmaf(xr[2], W1s[2 * 64 + d],
                        fmaf(xr[1], W1s[1 * 64 + d], xr[0] * W1s[d]));
            const float* pr = points + (size_t)r * 64;
            #pragma unroll 8
            for (int c = 0; c < 64; c++)
                acc = fmaf(pr[c], W1s[(3 + c) * 64 + d], acc);
            g_pre1[e] = acc;
        }
    }
}

// ---------------------------------------------------------------------------
// K2: query_ball — first 32 indices (ascending) with d <= R^2, pad with first
// ---------------------------------------------------------------------------
extern "C" __global__ void __launch_bounds__(256)
k_query(const float* __restrict__ xyz, float* __restrict__ out_idx)
{
    extern __shared__ float sm[];
    float* sx = sm;
    float* sy = sm + NN;
    float* sz = sm + 2 * NN;
    int b = blockIdx.x >> 3;
    int blk = blockIdx.x & 7;

    const float* xb = xyz + (size_t)b * NN * 3;
    for (int i = threadIdx.x; i < NN * 3; i += 256) {
        int n = i / 3, c = i - n * 3;
        ((c == 0) ? sx : (c == 1) ? sy : sz)[n] = xb[i];
    }
    __syncthreads();

    int warp = threadIdx.x >> 5, lane = threadIdx.x & 31;
    const float R2 = 0.04f;  // float-rounded 0.04, matches JAX weak-typed radius^2

    for (int q = 0; q < 16; q++) {
        int s = blk * 128 + warp * 16 + q;
        int cb = b * NPT + s;
        float cx = g_new_xyz[cb * 3], cy = g_new_xyz[cb * 3 + 1], cz = g_new_xyz[cb * 3 + 2];
        int base = cb * NSMP;
        int cnt = 0, first = 0;
        for (int ch = 0; ch < NN / 32; ch++) {
            int p = ch * 32 + lane;
            float dx = __fadd_rn(sx[p], -cx);
            float dy = __fadd_rn(sy[p], -cy);
            float dz = __fadd_rn(sz[p], -cz);
            float d = __fadd_rn(__fadd_rn(__fmul_rn(dx, dx), __fmul_rn(dy, dy)),
                                __fmul_rn(dz, dz));
            bool ok = (d <= R2);
            unsigned m = __ballot_sync(0xffffffffu, ok);
            if (m) {
                if (cnt == 0) first = ch * 32 + __ffs(m) - 1;
                int pos = cnt + __popc(m & ((1u << lane) - 1u));
                if (ok && pos < NSMP) {
                    g_idx[base + pos] = p;
                    out_idx[base + pos] = (float)p;
                }
                cnt += __popc(m);
                if (cnt >= NSMP) break;
            }
        }
        if (cnt < NSMP) {
            int slot = cnt + lane;
            if (slot < NSMP) {
                g_idx[base + slot] = first;
                out_idx[base + slot] = (float)first;
            }
        }
    }
}

// ---------------------------------------------------------------------------
// K3: per-centroid MLP (64->64->128) + max over 32 samples
//     one warp per centroid, lane = sample; h1 = relu(pre1[idx] + coff)
// ---------------------------------------------------------------------------
extern "C" __global__ void __launch_bounds__(256, 1)
k_mlp(const float* __restrict__ W2, const float* __restrict__ b2,
      const float* __restrict__ W3, const float* __restrict__ b3,
      const float* __restrict__ W1, const float* __restrict__ b1,
      float* __restrict__ out_pts)
{
    extern __shared__ float sm[];
    float* W2s  = sm;            // 4096
    float* W3s  = sm + 4096;     // 8192
    float* W1x  = sm + 12288;    // 192 (first 3 rows of W1)
    float* b1s  = sm + 12480;    // 64
    float* b2s  = sm + 12544;    // 64
    float* b3s  = sm + 12608;    // 128
    float* coffs = sm + 12736;   // 8 warps * 64

    int tid = threadIdx.x;
    int warp = tid >> 5, lane = tid & 31;
    int cent = blockIdx.x * 8 + warp;          // 0 .. 16383
    int b = cent >> 10;

    // kick off the dependent index load before the smem staging barrier
    int p = g_idx[cent * NSMP + lane];

    for (int i = tid; i < 4096; i += 256) W2s[i] = W2[i];
    for (int i = tid; i < 8192; i += 256) W3s[i] = W3[i];
    if (tid < 192) W1x[tid] = W1[tid];
    if (tid < 64) { b1s[tid] = b1[tid]; b2s[tid] = b2[tid]; }
    if (tid < 128) b3s[tid] = b3[tid];
    __syncthreads();

    // centroid offset: b1 - new_xyz @ W1[:3]
    float cx = g_new_xyz[cent * 3], cy = g_new_xyz[cent * 3 + 1], cz = g_new_xyz[cent * 3 + 2];
    float* co = coffs + warp * 64;
    #pragma unroll
    for (int r = 0; r < 2; r++) {
        int d = lane + r * 32;
        co[d] = b1s[d] - (cx * W1x[d] + cy * W1x[64 + d] + cz * W1x[128 + d]);
    }
    __syncwarp();

    const float4* row = (const float4*)(g_pre1 + ((size_t)(b * NN + p)) * 64);

    float h[64];
    #pragma unroll
    for (int iv = 0; iv < 16; iv++) {
        float4 v = row[iv];
        h[iv * 4 + 0] = fmaxf(v.x + co[iv * 4 + 0], 0.0f);
        h[iv * 4 + 1] = fmaxf(v.y + co[iv * 4 + 1], 0.0f);
        h[iv * 4 + 2] = fmaxf(v.z + co[iv * 4 + 2], 0.0f);
        h[iv * 4 + 3] = fmaxf(v.w + co[iv * 4 + 3], 0.0f);
    }

    // layer 2: h2 = relu(h1 @ W2 + b2)
    float a[64];
    #pragma unroll
    for (int j = 0; j < 64; j++) a[j] = b2s[j];
    #pragma unroll
    for (int i = 0; i < 64; i++) {
        float hi = h[i];
        const float4* wr = (const float4*)(W2s + i * 64);
        #pragma unroll
        for (int jv = 0; jv < 16; jv++) {
            float4 w = wr[jv];
            a[jv * 4 + 0] = fmaf(hi, w.x, a[jv * 4 + 0]);
            a[jv * 4 + 1] = fmaf(hi, w.y, a[jv * 4 + 1]);
            a[jv * 4 + 2] = fmaf(hi, w.z, a[jv * 4 + 2]);
            a[jv * 4 + 3] = fmaf(hi, w.w, a[jv * 4 + 3]);
        }
    }
    #pragma unroll
    for (int j = 0; j < 64; j++) h[j] = fmaxf(a[j], 0.0f);

    // layer 3 in 4 chunks of 32 outputs + cross-lane max
    #pragma unroll
    for (int m = 0; m < 4; m++) {
        float c[32];
        #pragma unroll
        for (int j = 0; j < 32; j++) c[j] = b3s[m * 32 + j];
        #pragma unroll
        for (int i = 0; i < 64; i++) {
            float hi = h[i];
            const float4* wr = (const float4*)(W3s + i * 128 + m * 32);
            #pragma unroll
            for (int jv = 0; jv < 8; jv++) {
                float4 w = wr[jv];
                c[jv * 4 + 0] = fmaf(hi, w.x, c[jv * 4 + 0]);
                c[jv * 4 + 1] = fmaf(hi, w.y, c[jv * 4 + 1]);
                c[jv * 4 + 2] = fmaf(hi, w.z, c[jv * 4 + 2]);
                c[jv * 4 + 3] = fmaf(hi, w.w, c[jv * 4 + 3]);
            }
        }
        #pragma unroll
        for (int j = 0; j < 32; j++) c[j] = fmaxf(c[j], 0.0f);

        // register-halving max reduce: lane l ends with channel m*32+l
        {
            bool up = (lane & 16) != 0;
            #pragma unroll
            for (int m2 = 0; m2 < 16; m2++) {
                float keep = up ? c[m2 + 16] : c[m2];
                float send = up ? c[m2] : c[m2 + 16];
                c[m2] = fmaxf(keep, __shfl_xor_sync(0xffffffffu, send, 16));
            }
        }
        {
            bool up = (lane & 8) != 0;
            #pragma unroll
            for (int m2 = 0; m2 < 8; m2++) {
                float keep = up ? c[m2 + 8] : c[m2];
                float send = up ? c[m2] : c[m2 + 8];
                c[m2] = fmaxf(keep, __shfl_xor_sync(0xffffffffu, send, 8));
            }
        }
        {
            bool up = (lane & 4) != 0;
            #pragma unroll
            for (int m2 = 0; m2 < 4; m2++) {
                float keep = up ? c[m2 + 4] : c[m2];
                float send = up ? c[m2] : c[m2 + 4];
                c[m2] = fmaxf(keep, __shfl_xor_sync(0xffffffffu, send, 4));
            }
        }
        {
            bool up = (lane & 2) != 0;
            #pragma unroll
            for (int m2 = 0; m2 < 2; m2++) {
                float keep = up ? c[m2 + 2] : c[m2];
                float send = up ? c[m2] : c[m2 + 2];
                c[m2] = fmaxf(keep, __shfl_xor_sync(0xffffffffu, send, 2));
            }
        }
        {
            bool up = (lane & 1) != 0;
            float keep = up ? c[1] : c[0];
            float send = up ? c[0] : c[1];
            c[0] = fmaxf(keep, __shfl_xor_sync(0xffffffffu, send, 1));
        }
        out_pts[(size_t)cent * 128 + m * 32 + lane] = c[0];
    }
}

// ---------------------------------------------------------------------------
extern "C" void kernel_launch(void* const* d_in, const int* in_sizes, int n_in,
                              void* d_out, int out_size)
{
    const float* xyz    = (const float*)d_in[0];
    const float* points = (const float*)d_in[1];
    const float* W1     = (const float*)d_in[2];
    const float* b1     = (const float*)d_in[3];
    const float* W2     = (const float*)d_in[4];
    const float* b2     = (const float*)d_in[5];
    const float* W3     = (const float*)d_in[6];
    const float* b3     = (const float*)d_in[7];

    float* out = (float*)d_out;
    float* out_xyz = out;                                  // 16*1024*3
    float* out_pts = out + BB * NPT * 3;                   // 16*1024*128
    float* out_idx = out + BB * NPT * 3 + BB * NPT * 128;  // 16*1024*32

    cudaFuncSetAttribute(k_fps_pre1, cudaFuncAttributeMaxDynamicSharedMemorySize, 50176);
    cudaFuncSetAttribute(k_query,    cudaFuncAttributeMaxDynamicSharedMemorySize, 49152);
    cudaFuncSetAttribute(k_mlp,      cudaFuncAttributeMaxDynamicSharedMemorySize, 53248);

    k_fps_pre1<<<148, 1024, 50176>>>(xyz, points, W1, out_xyz);
    k_query<<<128, 256, 49152>>>(xyz, out_idx);
    k_mlp<<<2048, 256, 53248>>>(W2, b2, W3, b3, W1, b1, out_pts);
}

// round 3
// speedup vs baseline: 1.5910x; 1.5910x over previous
#include <cuda_runtime.h>

#define BB 16
#define NN 4096
#define CC 64
#define NPT 1024
#define NSMP 32

typedef unsigned long long u64;

// ---------------- scratch (device globals; no allocations allowed) ----------
__device__ __align__(16) float g_pre1[BB * NN * CC];   // 16 MB: per-point layer-1 pre-activation
__device__ float g_new_xyz[BB * NPT * 3];
__device__ int   g_idx[BB * NPT * NSMP];

// ---------------- helpers ---------------------------------------------------
__device__ __forceinline__ unsigned redux_max_u32(unsigned v) {
    unsigned r;
    asm("redux.sync.max.u32 %0, %1, 0xffffffff;" : "=r"(r) : "r"(v));
    return r;
}
__device__ __forceinline__ unsigned redux_min_u32(unsigned v) {
    unsigned r;
    asm("redux.sync.min.u32 %0, %1, 0xffffffff;" : "=r"(r) : "r"(v));
    return r;
}
__device__ __forceinline__ u64 pack2(float lo, float hi) {
    u64 r;
    asm("mov.b64 %0, {%1, %2};" : "=l"(r) : "f"(lo), "f"(hi));
    return r;
}
__device__ __forceinline__ void unpack2(u64 v, float& lo, float& hi) {
    asm("mov.b64 {%0, %1}, %2;" : "=f"(lo), "=f"(hi) : "l"(v));
}
__device__ __forceinline__ u64 fma2(u64 a, u64 b, u64 c) {
    u64 r;
    asm("fma.rn.f32x2 %0, %1, %2, %3;" : "=l"(r) : "l"(a), "l"(b), "l"(c));
    return r;
}

// ---------------------------------------------------------------------------
// K1: blocks [0,16): farthest point sampling (one block per batch)
//     blocks [16,..): pre1 = xyz @ W1[:3] + points @ W1[3:]  (per original point)
// ---------------------------------------------------------------------------
extern "C" __global__ void __launch_bounds__(1024)
k_fps_pre1(const float* __restrict__ xyz, const float* __restrict__ points,
           const float* __restrict__ W1, float* __restrict__ out_xyz)
{
    extern __shared__ float sm[];
    int t = threadIdx.x;

    if (blockIdx.x < BB) {
        // ---------------- FPS ----------------
        int b = blockIdx.x;
        float* sx = sm;
        float* sy = sm + NN;
        float* sz = sm + 2 * NN;
        uint2* spair = (uint2*)(sm + 3 * NN);   // 2 buffers x 32 (wmaxbits, widx)

        const float* xb = xyz + (size_t)b * NN * 3;
        for (int i = t; i < NN * 3; i += 1024) {
            int n = i / 3, c = i - n * 3;
            float v = xb[i];
            ((c == 0) ? sx : (c == 1) ? sy : sz)[n] = v;
        }
        __syncthreads();

        float px[4], py[4], pz[4], dd[4];
        #pragma unroll
        for (int j = 0; j < 4; j++) {
            int p = t + j * 1024;
            px[j] = sx[p]; py[j] = sy[p]; pz[j] = sz[p];
            dd[j] = 1e10f;
        }

        int warp = t >> 5, lane = t & 31;
        int far = 0;
        int myfps = 0;
        float cx = sx[0], cy = sy[0], cz = sz[0];

        for (int s = 0; s < NPT; s++) {
            if (s == t) myfps = far;   // fps index of step s (register, per thread)

            // thread-local argmax over 4 points (strict >, ascending j -> first max)
            unsigned lb = 0; int li = t;
            #pragma unroll
            for (int j = 0; j < 4; j++) {
                // match XLA: square via mul, left-assoc add tree, no fma contraction
                float dx = __fadd_rn(px[j], -cx);
                float dy = __fadd_rn(py[j], -cy);
                float dz = __fadd_rn(pz[j], -cz);
                float d = __fadd_rn(__fadd_rn(__fmul_rn(dx, dx), __fmul_rn(dy, dy)),
                                    __fmul_rn(dz, dz));
                dd[j] = fminf(dd[j], d);
                unsigned bits = __float_as_uint(dd[j]);  // dd >= 0: bits monotone
                if (j == 0) { lb = bits; li = t; }
                else if (bits > lb) { lb = bits; li = t + j * 1024; }
            }
            // warp argmax: max bits, then min index among ties (exact first-max)
            unsigned wmax = redux_max_u32(lb);
            unsigned cand = (lb == wmax) ? (unsigned)li : 0xffffffffu;
            unsigned wbesti = redux_min_u32(cand);
            if (lane == 0) spair[(s & 1) * 32 + warp] = make_uint2(wmax, wbesti);
            __syncthreads();
            // every warp redundantly reduces the 32 warp results
            uint2 pr = spair[(s & 1) * 32 + lane];
            unsigned gmax = redux_max_u32(pr.x);
            unsigned c2 = (pr.x == gmax) ? pr.y : 0xffffffffu;
            far = (int)redux_min_u32(c2);
            cx = sx[far]; cy = sy[far]; cz = sz[far];
        }

        // gather new_xyz (thread t holds fps index of step t)
        {
            float nx = sx[myfps], ny = sy[myfps], nz = sz[myfps];
            int o = (b * NPT + t) * 3;
            g_new_xyz[o] = nx; g_new_xyz[o + 1] = ny; g_new_xyz[o + 2] = nz;
            out_xyz[o] = nx; out_xyz[o + 1] = ny; out_xyz[o + 2] = nz;
        }
    } else {
        // ---------------- pre1 ----------------
        float* W1s = sm; // 67*64 floats
        for (int i = t; i < 67 * 64; i += 1024) W1s[i] = W1[i];
        __syncthreads();
        int nb = gridDim.x - BB;
        const int total = BB * NN * CC;
        for (int e = (blockIdx.x - BB) * 1024 + t; e < total; e += nb * 1024) {
            int r = e >> 6;       // global point row (b*N + n)
            int d = e & 63;       // output channel
            const float* xr = xyz + (size_t)r * 3;
            float acc = fmaf(xr[2], W1s[2 * 64 + d],
                        fmaf(xr[1], W1s[1 * 64 + d], xr[0] * W1s[d]));
            const float* pr = points + (size_t)r * 64;
            #pragma unroll 8
            for (int c = 0; c < 64; c++)
                acc = fmaf(pr[c], W1s[(3 + c) * 64 + d], acc);
            g_pre1[e] = acc;
        }
    }
}

// ---------------------------------------------------------------------------
// K2: query_ball — first 32 indices (ascending) with d <= R^2, pad with first
// ---------------------------------------------------------------------------
extern "C" __global__ void __launch_bounds__(256)
k_query(const float* __restrict__ xyz, float* __restrict__ out_idx)
{
    extern __shared__ float sm[];
    float* sx = sm;
    float* sy = sm + NN;
    float* sz = sm + 2 * NN;
    int b = blockIdx.x >> 3;
    int blk = blockIdx.x & 7;

    const float* xb = xyz + (size_t)b * NN * 3;
    for (int i = threadIdx.x; i < NN * 3; i += 256) {
        int n = i / 3, c = i - n * 3;
        ((c == 0) ? sx : (c == 1) ? sy : sz)[n] = xb[i];
    }
    __syncthreads();

    int warp = threadIdx.x >> 5, lane = threadIdx.x & 31;
    const float R2 = 0.04f;  // float-rounded 0.04, matches JAX weak-typed radius^2

    for (int q = 0; q < 16; q++) {
        int s = blk * 128 + warp * 16 + q;
        int cb = b * NPT + s;
        float cx = g_new_xyz[cb * 3], cy = g_new_xyz[cb * 3 + 1], cz = g_new_xyz[cb * 3 + 2];
        int base = cb * NSMP;
        int cnt = 0, first = 0;
        for (int ch = 0; ch < NN / 32; ch++) {
            int p = ch * 32 + lane;
            float dx = __fadd_rn(sx[p], -cx);
            float dy = __fadd_rn(sy[p], -cy);
            float dz = __fadd_rn(sz[p], -cz);
            float d = __fadd_rn(__fadd_rn(__fmul_rn(dx, dx), __fmul_rn(dy, dy)),
                                __fmul_rn(dz, dz));
            bool ok = (d <= R2);
            unsigned m = __ballot_sync(0xffffffffu, ok);
            if (m) {
                if (cnt == 0) first = ch * 32 + __ffs(m) - 1;
                int pos = cnt + __popc(m & ((1u << lane) - 1u));
                if (ok && pos < NSMP) {
                    g_idx[base + pos] = p;
                    out_idx[base + pos] = (float)p;
                }
                cnt += __popc(m);
                if (cnt >= NSMP) break;
            }
        }
        if (cnt < NSMP) {
            int slot = cnt + lane;
            if (slot < NSMP) {
                g_idx[base + slot] = first;
                out_idx[base + slot] = (float)first;
            }
        }
    }
}

// ---------------------------------------------------------------------------
// K3: per-centroid MLP (64->64->128) + max over 32 samples
//     one warp per centroid, lane = sample; h1 = relu(pre1[idx] + coff)
//     GEMM core uses packed fma.rn.f32x2 (2 FMAs / instr)
// ---------------------------------------------------------------------------
extern "C" __global__ void __launch_bounds__(256, 1)
k_mlp(const float* __restrict__ W2, const float* __restrict__ b2,
      const float* __restrict__ W3, const float* __restrict__ b3,
      const float* __restrict__ W1, const float* __restrict__ b1,
      float* __restrict__ out_pts)
{
    extern __shared__ float sm[];
    float* W2s  = sm;            // 4096
    float* W3s  = sm + 4096;     // 8192
    float* W1x  = sm + 12288;    // 192 (first 3 rows of W1)
    float* b1s  = sm + 12480;    // 64
    float* b2s  = sm + 12544;    // 64
    float* b3s  = sm + 12608;    // 128
    float* coffs = sm + 12736;   // 8 warps * 64

    int tid = threadIdx.x;
    int warp = tid >> 5, lane = tid & 31;
    int cent = blockIdx.x * 8 + warp;          // 0 .. 16383
    int b = cent >> 10;

    // kick off the dependent index load before the smem staging barrier
    int p = g_idx[cent * NSMP + lane];

    for (int i = tid; i < 4096; i += 256) W2s[i] = W2[i];
    for (int i = tid; i < 8192; i += 256) W3s[i] = W3[i];
    if (tid < 192) W1x[tid] = W1[tid];
    if (tid < 64) { b1s[tid] = b1[tid]; b2s[tid] = b2[tid]; }
    if (tid < 128) b3s[tid] = b3[tid];
    __syncthreads();

    // centroid offset: b1 - new_xyz @ W1[:3]
    float cx = g_new_xyz[cent * 3], cy = g_new_xyz[cent * 3 + 1], cz = g_new_xyz[cent * 3 + 2];
    float* co = coffs + warp * 64;
    #pragma unroll
    for (int r = 0; r < 2; r++) {
        int d = lane + r * 32;
        co[d] = b1s[d] - (cx * W1x[d] + cy * W1x[64 + d] + cz * W1x[128 + d]);
    }
    __syncwarp();

    const float4* row = (const float4*)(g_pre1 + ((size_t)(b * NN + p)) * 64);

    float h[64];
    #pragma unroll
    for (int iv = 0; iv < 16; iv++) {
        float4 v = row[iv];
        h[iv * 4 + 0] = fmaxf(v.x + co[iv * 4 + 0], 0.0f);
        h[iv * 4 + 1] = fmaxf(v.y + co[iv * 4 + 1], 0.0f);
        h[iv * 4 + 2] = fmaxf(v.z + co[iv * 4 + 2], 0.0f);
        h[iv * 4 + 3] = fmaxf(v.w + co[iv * 4 + 3], 0.0f);
    }

    // layer 2: h2 = relu(h1 @ W2 + b2), packed f32x2
    {
        u64 acc[32];
        #pragma unroll
        for (int j = 0; j < 32; j++) acc[j] = pack2(b2s[2 * j], b2s[2 * j + 1]);
        #pragma unroll
        for (int i = 0; i < 64; i++) {
            u64 hh = pack2(h[i], h[i]);
            const ulonglong2* wr = (const ulonglong2*)(W2s + i * 64);
            #pragma unroll
            for (int jv = 0; jv < 16; jv++) {
                ulonglong2 w = wr[jv];
                acc[2 * jv]     = fma2(hh, w.x, acc[2 * jv]);
                acc[2 * jv + 1] = fma2(hh, w.y, acc[2 * jv + 1]);
            }
        }
        #pragma unroll
        for (int j = 0; j < 32; j++) {
            float lo, hi;
            unpack2(acc[j], lo, hi);
            h[2 * j]     = fmaxf(lo, 0.0f);
            h[2 * j + 1] = fmaxf(hi, 0.0f);
        }
    }

    // layer 3 in 4 chunks of 32 outputs + cross-lane max
    #pragma unroll
    for (int m = 0; m < 4; m++) {
        u64 cc[16];
        #pragma unroll
        for (int j = 0; j < 16; j++) cc[j] = pack2(b3s[m * 32 + 2 * j], b3s[m * 32 + 2 * j + 1]);
        #pragma unroll
        for (int i = 0; i < 64; i++) {
            u64 hh = pack2(h[i], h[i]);
            const ulonglong2* wr = (const ulonglong2*)(W3s + i * 128 + m * 32);
            #pragma unroll
            for (int jv = 0; jv < 8; jv++) {
                ulonglong2 w = wr[jv];
                cc[2 * jv]     = fma2(hh, w.x, cc[2 * jv]);
                cc[2 * jv + 1] = fma2(hh, w.y, cc[2 * jv + 1]);
            }
        }
        float c[32];
        #pragma unroll
        for (int j = 0; j < 16; j++) {
            float lo, hi;
            unpack2(cc[j], lo, hi);
            c[2 * j]     = fmaxf(lo, 0.0f);
            c[2 * j + 1] = fmaxf(hi, 0.0f);
        }

        // register-halving max reduce: lane l ends with channel m*32+l
        {
            bool up = (lane & 16) != 0;
            #pragma unroll
            for (int m2 = 0; m2 < 16; m2++) {
                float keep = up ? c[m2 + 16] : c[m2];
                float send = up ? c[m2] : c[m2 + 16];
                c[m2] = fmaxf(keep, __shfl_xor_sync(0xffffffffu, send, 16));
            }
        }
        {
            bool up = (lane & 8) != 0;
            #pragma unroll
            for (int m2 = 0; m2 < 8; m2++) {
                float keep = up ? c[m2 + 8] : c[m2];
                float send = up ? c[m2] : c[m2 + 8];
                c[m2] = fmaxf(keep, __shfl_xor_sync(0xffffffffu, send, 8));
            }
        }
        {
            bool up = (lane & 4) != 0;
            #pragma unroll
            for (int m2 = 0; m2 < 4; m2++) {
                float keep = up ? c[m2 + 4] : c[m2];
                float send = up ? c[m2] : c[m2 + 4];
                c[m2] = fmaxf(keep, __shfl_xor_sync(0xffffffffu, send, 4));
            }
        }
        {
            bool up = (lane & 2) != 0;
            #pragma unroll
            for (int m2 = 0; m2 < 2; m2++) {
                float keep = up ? c[m2 + 2] : c[m2];
                float send = up ? c[m2] : c[m2 + 2];
                c[m2] = fmaxf(keep, __shfl_xor_sync(0xffffffffu, send, 2));
            }
        }
        {
            bool up = (lane & 1) != 0;
            float keep = up ? c[1] : c[0];
            float send = up ? c[0] : c[1];
            c[0] = fmaxf(keep, __shfl_xor_sync(0xffffffffu, send, 1));
        }
        out_pts[(size_t)cent * 128 + m * 32 + lane] = c[0];
    }
}

// ---------------------------------------------------------------------------
extern "C" void kernel_launch(void* const* d_in, const int* in_sizes, int n_in,
                              void* d_out, int out_size)
{
    const float* xyz    = (const float*)d_in[0];
    const float* points = (const float*)d_in[1];
    const float* W1     = (const float*)d_in[2];
    const float* b1     = (const float*)d_in[3];
    const float* W2     = (const float*)d_in[4];
    const float* b2     = (const float*)d_in[5];
    const float* W3     = (const float*)d_in[6];
    const float* b3     = (const float*)d_in[7];

    float* out = (float*)d_out;
    float* out_xyz = out;                                  // 16*1024*3
    float* out_pts = out + BB * NPT * 3;                   // 16*1024*128
    float* out_idx = out + BB * NPT * 3 + BB * NPT * 128;  // 16*1024*32

    cudaFuncSetAttribute(k_fps_pre1, cudaFuncAttributeMaxDynamicSharedMemorySize, 50176);
    cudaFuncSetAttribute(k_query,    cudaFuncAttributeMaxDynamicSharedMemorySize, 49152);
    cudaFuncSetAttribute(k_mlp,      cudaFuncAttributeMaxDynamicSharedMemorySize, 53248);

    k_fps_pre1<<<148, 1024, 50176>>>(xyz, points, W1, out_xyz);
    k_query<<<128, 256, 49152>>>(xyz, out_idx);
    k_mlp<<<2048, 256, 53248>>>(W2, b2, W3, b3, W1, b1, out_pts);
}

// round 4
// speedup vs baseline: 2.0336x; 1.2782x over previous
#include <cuda_runtime.h>

#define BB 16
#define NN 4096
#define CC 64
#define NPT 1024
#define NSMP 32

typedef unsigned long long u64;

// ---------------- scratch (device globals; no allocations allowed) ----------
__device__ __align__(16) float g_pre1[BB * NN * CC];   // 16 MB: per-point layer-1 pre-activation
__device__ float g_new_xyz[BB * NPT * 3];
__device__ int   g_idx[BB * NPT * NSMP];

// ---------------- helpers ---------------------------------------------------
__device__ __forceinline__ unsigned redux_max_u32(unsigned v) {
    unsigned r;
    asm("redux.sync.max.u32 %0, %1, 0xffffffff;" : "=r"(r) : "r"(v));
    return r;
}
__device__ __forceinline__ unsigned redux_min_u32(unsigned v) {
    unsigned r;
    asm("redux.sync.min.u32 %0, %1, 0xffffffff;" : "=r"(r) : "r"(v));
    return r;
}
__device__ __forceinline__ u64 pack2(float lo, float hi) {
    u64 r;
    asm("mov.b64 %0, {%1, %2};" : "=l"(r) : "f"(lo), "f"(hi));
    return r;
}
__device__ __forceinline__ void unpack2(u64 v, float& lo, float& hi) {
    asm("mov.b64 {%0, %1}, %2;" : "=f"(lo), "=f"(hi) : "l"(v));
}
__device__ __forceinline__ u64 fma2(u64 a, u64 b, u64 c) {
    u64 r;
    asm("fma.rn.f32x2 %0, %1, %2, %3;" : "=l"(r) : "l"(a), "l"(b), "l"(c));
    return r;
}
__device__ __forceinline__ u64 add2(u64 a, u64 b) {
    u64 r;
    asm("add.rn.f32x2 %0, %1, %2;" : "=l"(r) : "l"(a), "l"(b));
    return r;
}
__device__ __forceinline__ u64 mul2(u64 a, u64 b) {
    u64 r;
    asm("mul.rn.f32x2 %0, %1, %2;" : "=l"(r) : "l"(a), "l"(b));
    return r;
}

// ---------------------------------------------------------------------------
// K1: blocks [0,16): farthest point sampling (one block per batch, 512 thr)
//     blocks [16,..): pre1 = xyz @ W1[:3] + points @ W1[3:]  (per original point)
// 116KB dyn smem per block -> exactly one block per SM (FPS isolation)
// ---------------------------------------------------------------------------
extern "C" __global__ void __launch_bounds__(512)
k_fps_pre1(const float* __restrict__ xyz, const float* __restrict__ points,
           const float* __restrict__ W1, float* __restrict__ out_xyz)
{
    extern __shared__ float sm[];
    int t = threadIdx.x;

    if (blockIdx.x < BB) {
        // ---------------- FPS ----------------
        int b = blockIdx.x;
        float* sx = sm;
        float* sy = sm + NN;
        float* sz = sm + 2 * NN;
        uint2* spair = (uint2*)(sm + 3 * NN);   // 2 buffers x 16 (wmaxbits, widx)

        const float* xb = xyz + (size_t)b * NN * 3;
        for (int i = t; i < NN * 3; i += 512) {
            int n = i / 3, c = i - n * 3;
            float v = xb[i];
            ((c == 0) ? sx : (c == 1) ? sy : sz)[n] = v;
        }
        __syncthreads();

        // 8 points per thread: indices t + k*512, packed in pairs (2a, 2a+1)
        float dd[8];
        u64 PX[4], PY[4], PZ[4];
        #pragma unroll
        for (int a = 0; a < 4; a++) {
            int p0 = t + (2 * a) * 512, p1 = t + (2 * a + 1) * 512;
            PX[a] = pack2(sx[p0], sx[p1]);
            PY[a] = pack2(sy[p0], sy[p1]);
            PZ[a] = pack2(sz[p0], sz[p1]);
            dd[2 * a] = 1e10f; dd[2 * a + 1] = 1e10f;
        }

        int warp = t >> 5, lane = t & 31;
        int far = 0;
        int myfps0 = 0, myfps1 = 0;
        float cx = sx[0], cy = sy[0], cz = sz[0];

        for (int s = 0; s < NPT; s++) {
            if (s == t) myfps0 = far;          // centroid s (first half)
            if (s == t + 512) myfps1 = far;    // centroid s (second half)

            float ncxf = -cx, ncyf = -cy, nczf = -cz;
            u64 ncx = pack2(ncxf, ncxf);
            u64 ncy = pack2(ncyf, ncyf);
            u64 ncz = pack2(nczf, nczf);

            // packed distance, exact per-lane RN, same op order as XLA:
            // d = ((p-c).x^2 + (p-c).y^2) + (p-c).z^2   (mul then add, no fma)
            unsigned lb = 0; int li = t;
            #pragma unroll
            for (int a = 0; a < 4; a++) {
                u64 dx = add2(PX[a], ncx);
                u64 dy = add2(PY[a], ncy);
                u64 dz = add2(PZ[a], ncz);
                u64 d2 = add2(add2(mul2(dx, dx), mul2(dy, dy)), mul2(dz, dz));
                float dlo, dhi;
                unpack2(d2, dlo, dhi);
                dd[2 * a]     = fminf(dd[2 * a], dlo);
                dd[2 * a + 1] = fminf(dd[2 * a + 1], dhi);
                unsigned blo = __float_as_uint(dd[2 * a]);      // dd>=0: monotone
                unsigned bhi = __float_as_uint(dd[2 * a + 1]);
                if (a == 0) { lb = blo; li = t; }
                else if (blo > lb) { lb = blo; li = t + (2 * a) * 512; }
                if (bhi > lb) { lb = bhi; li = t + (2 * a + 1) * 512; }
            }
            // warp argmax: max bits, then min index among ties (exact first-max)
            unsigned wmax = redux_max_u32(lb);
            unsigned cand = (lb == wmax) ? (unsigned)li : 0xffffffffu;
            unsigned wbesti = redux_min_u32(cand);
            if (lane == 0) spair[(s & 1) * 16 + warp] = make_uint2(wmax, wbesti);
            __syncthreads();
            // every warp redundantly reduces the 16 warp results (lane&15 dup)
            uint2 pr = spair[(s & 1) * 16 + (lane & 15)];
            unsigned gmax = redux_max_u32(pr.x);
            unsigned c2 = (pr.x == gmax) ? pr.y : 0xffffffffu;
            far = (int)redux_min_u32(c2);
            cx = sx[far]; cy = sy[far]; cz = sz[far];
        }

        // thread t holds fps indices of centroids t and t+512
        {
            int o = (b * NPT + t) * 3;
            float nx = sx[myfps0], ny = sy[myfps0], nz = sz[myfps0];
            g_new_xyz[o] = nx; g_new_xyz[o + 1] = ny; g_new_xyz[o + 2] = nz;
            out_xyz[o] = nx; out_xyz[o + 1] = ny; out_xyz[o + 2] = nz;
            int o2 = (b * NPT + t + 512) * 3;
            float mx = sx[myfps1], my = sy[myfps1], mz = sz[myfps1];
            g_new_xyz[o2] = mx; g_new_xyz[o2 + 1] = my; g_new_xyz[o2 + 2] = mz;
            out_xyz[o2] = mx; out_xyz[o2 + 1] = my; out_xyz[o2 + 2] = mz;
        }
    } else {
        // ---------------- pre1 ----------------
        float* W1s = sm; // 67*64 floats
        for (int i = t; i < 67 * 64; i += 512) W1s[i] = W1[i];
        __syncthreads();
        int nb = gridDim.x - BB;
        const int total = BB * NN * CC;
        for (int e = (blockIdx.x - BB) * 512 + t; e < total; e += nb * 512) {
            int r = e >> 6;       // global point row (b*N + n)
            int d = e & 63;       // output channel
            const float* xr = xyz + (size_t)r * 3;
            float acc = fmaf(xr[2], W1s[2 * 64 + d],
                        fmaf(xr[1], W1s[1 * 64 + d], xr[0] * W1s[d]));
            const float* pr = points + (size_t)r * 64;
            #pragma unroll 8
            for (int c = 0; c < 64; c++)
                acc = fmaf(pr[c], W1s[(3 + c) * 64 + d], acc);
            g_pre1[e] = acc;
        }
    }
}

// ---------------------------------------------------------------------------
// K2: query_ball — first 32 indices (ascending) with d <= R^2, pad with first
// ---------------------------------------------------------------------------
extern "C" __global__ void __launch_bounds__(256)
k_query(const float* __restrict__ xyz, float* __restrict__ out_idx)
{
    extern __shared__ float sm[];
    float* sx = sm;
    float* sy = sm + NN;
    float* sz = sm + 2 * NN;
    int b = blockIdx.x >> 4;
    int blk = blockIdx.x & 15;

    const float* xb = xyz + (size_t)b * NN * 3;
    for (int i = threadIdx.x; i < NN * 3; i += 256) {
        int n = i / 3, c = i - n * 3;
        ((c == 0) ? sx : (c == 1) ? sy : sz)[n] = xb[i];
    }
    __syncthreads();

    int warp = threadIdx.x >> 5, lane = threadIdx.x & 31;
    const float R2 = 0.04f;  // float-rounded 0.04, matches JAX weak-typed radius^2

    for (int q = 0; q < 8; q++) {
        int s = blk * 64 + warp * 8 + q;
        int cb = b * NPT + s;
        float cx = g_new_xyz[cb * 3], cy = g_new_xyz[cb * 3 + 1], cz = g_new_xyz[cb * 3 + 2];
        int base = cb * NSMP;
        int cnt = 0, first = 0;
        for (int ch = 0; ch < NN / 32; ch++) {
            int p = ch * 32 + lane;
            float dx = __fadd_rn(sx[p], -cx);
            float dy = __fadd_rn(sy[p], -cy);
            float dz = __fadd_rn(sz[p], -cz);
            float d = __fadd_rn(__fadd_rn(__fmul_rn(dx, dx), __fmul_rn(dy, dy)),
                                __fmul_rn(dz, dz));
            bool ok = (d <= R2);
            unsigned m = __ballot_sync(0xffffffffu, ok);
            if (m) {
                if (cnt == 0) first = ch * 32 + __ffs(m) - 1;
                int pos = cnt + __popc(m & ((1u << lane) - 1u));
                if (ok && pos < NSMP) {
                    g_idx[base + pos] = p;
                    out_idx[base + pos] = (float)p;
                }
                cnt += __popc(m);
                if (cnt >= NSMP) break;
            }
        }
        if (cnt < NSMP) {
            int slot = cnt + lane;
            if (slot < NSMP) {
                g_idx[base + slot] = first;
                out_idx[base + slot] = (float)first;
            }
        }
    }
}

// ---------------------------------------------------------------------------
// K3: per-centroid MLP (64->64->128) + max over 32 samples
//     one warp per centroid, lane = sample; h1 = relu(pre1[idx] + coff)
//     GEMM core uses packed fma.rn.f32x2; 128-thr blocks, 3 blocks/SM
// ---------------------------------------------------------------------------
extern "C" __global__ void __launch_bounds__(128, 3)
k_mlp(const float* __restrict__ W2, const float* __restrict__ b2,
      const float* __restrict__ W3, const float* __restrict__ b3,
      const float* __restrict__ W1, const float* __restrict__ b1,
      float* __restrict__ out_pts)
{
    extern __shared__ float sm[];
    float* W2s  = sm;            // 4096
    float* W3s  = sm + 4096;     // 8192
    float* W1x  = sm + 12288;    // 192 (first 3 rows of W1)
    float* b1s  = sm + 12480;    // 64
    float* b2s  = sm + 12544;    // 64
    float* b3s  = sm + 12608;    // 128
    float* coffs = sm + 12736;   // 4 warps * 64

    int tid = threadIdx.x;
    int warp = tid >> 5, lane = tid & 31;
    int cent = blockIdx.x * 4 + warp;          // 0 .. 16383
    int b = cent >> 10;

    // kick off the dependent index load before the smem staging barrier
    int p = g_idx[cent * NSMP + lane];

    for (int i = tid; i < 4096; i += 128) W2s[i] = W2[i];
    for (int i = tid; i < 8192; i += 128) W3s[i] = W3[i];
    if (tid < 64) { W1x[tid] = W1[tid]; W1x[64 + tid] = W1[64 + tid]; W1x[128 + tid] = W1[128 + tid]; }
    if (tid < 64) { b1s[tid] = b1[tid]; b2s[tid] = b2[tid]; }
    if (tid >= 64) b3s[tid - 64] = b3[tid - 64];
    if (tid < 64) b3s[64 + tid] = b3[64 + tid];
    __syncthreads();

    // centroid offset: b1 - new_xyz @ W1[:3]
    float cx = g_new_xyz[cent * 3], cy = g_new_xyz[cent * 3 + 1], cz = g_new_xyz[cent * 3 + 2];
    float* co = coffs + warp * 64;
    #pragma unroll
    for (int r = 0; r < 2; r++) {
        int d = lane + r * 32;
        co[d] = b1s[d] - (cx * W1x[d] + cy * W1x[64 + d] + cz * W1x[128 + d]);
    }
    __syncwarp();

    const float4* row = (const float4*)(g_pre1 + ((size_t)(b * NN + p)) * 64);

    float h[64];
    #pragma unroll
    for (int iv = 0; iv < 16; iv++) {
        float4 v = row[iv];
        h[iv * 4 + 0] = fmaxf(v.x + co[iv * 4 + 0], 0.0f);
        h[iv * 4 + 1] = fmaxf(v.y + co[iv * 4 + 1], 0.0f);
        h[iv * 4 + 2] = fmaxf(v.z + co[iv * 4 + 2], 0.0f);
        h[iv * 4 + 3] = fmaxf(v.w + co[iv * 4 + 3], 0.0f);
    }

    // layer 2: h2 = relu(h1 @ W2 + b2), packed f32x2
    {
        u64 acc[32];
        #pragma unroll
        for (int j = 0; j < 32; j++) acc[j] = pack2(b2s[2 * j], b2s[2 * j + 1]);
        #pragma unroll
        for (int i = 0; i < 64; i++) {
            u64 hh = pack2(h[i], h[i]);
            const ulonglong2* wr = (const ulonglong2*)(W2s + i * 64);
            #pragma unroll
            for (int jv = 0; jv < 16; jv++) {
                ulonglong2 w = wr[jv];
                acc[2 * jv]     = fma2(hh, w.x, acc[2 * jv]);
                acc[2 * jv + 1] = fma2(hh, w.y, acc[2 * jv + 1]);
            }
        }
        #pragma unroll
        for (int j = 0; j < 32; j++) {
            float lo, hi;
            unpack2(acc[j], lo, hi);
            h[2 * j]     = fmaxf(lo, 0.0f);
            h[2 * j + 1] = fmaxf(hi, 0.0f);
        }
    }

    // layer 3 in 4 chunks of 32 outputs + cross-lane max
    #pragma unroll
    for (int m = 0; m < 4; m++) {
        u64 cc[16];
        #pragma unroll
        for (int j = 0; j < 16; j++) cc[j] = pack2(b3s[m * 32 + 2 * j], b3s[m * 32 + 2 * j + 1]);
        #pragma unroll
        for (int i = 0; i < 64; i++) {
            u64 hh = pack2(h[i], h[i]);
            const ulonglong2* wr = (const ulonglong2*)(W3s + i * 128 + m * 32);
            #pragma unroll
            for (int jv = 0; jv < 8; jv++) {
                ulonglong2 w = wr[jv];
                cc[2 * jv]     = fma2(hh, w.x, cc[2 * jv]);
                cc[2 * jv + 1] = fma2(hh, w.y, cc[2 * jv + 1]);
            }
        }
        float c[32];
        #pragma unroll
        for (int j = 0; j < 16; j++) {
            float lo, hi;
            unpack2(cc[j], lo, hi);
            c[2 * j]     = fmaxf(lo, 0.0f);
            c[2 * j + 1] = fmaxf(hi, 0.0f);
        }

        // register-halving max reduce: lane l ends with channel m*32+l
        {
            bool up = (lane & 16) != 0;
            #pragma unroll
            for (int m2 = 0; m2 < 16; m2++) {
                float keep = up ? c[m2 + 16] : c[m2];
                float send = up ? c[m2] : c[m2 + 16];
                c[m2] = fmaxf(keep, __shfl_xor_sync(0xffffffffu, send, 16));
            }
        }
        {
            bool up = (lane & 8) != 0;
            #pragma unroll
            for (int m2 = 0; m2 < 8; m2++) {
                float keep = up ? c[m2 + 8] : c[m2];
                float send = up ? c[m2] : c[m2 + 8];
                c[m2] = fmaxf(keep, __shfl_xor_sync(0xffffffffu, send, 8));
            }
        }
        {
            bool up = (lane & 4) != 0;
            #pragma unroll
            for (int m2 = 0; m2 < 4; m2++) {
                float keep = up ? c[m2 + 4] : c[m2];
                float send = up ? c[m2] : c[m2 + 4];
                c[m2] = fmaxf(keep, __shfl_xor_sync(0xffffffffu, send, 4));
            }
        }
        {
            bool up = (lane & 2) != 0;
            #pragma unroll
            for (int m2 = 0; m2 < 2; m2++) {
                float keep = up ? c[m2 + 2] : c[m2];
                float send = up ? c[m2] : c[m2 + 2];
                c[m2] = fmaxf(keep, __shfl_xor_sync(0xffffffffu, send, 2));
            }
        }
        {
            bool up = (lane & 1) != 0;
            float keep = up ? c[1] : c[0];
            float send = up ? c[0] : c[1];
            c[0] = fmaxf(keep, __shfl_xor_sync(0xffffffffu, send, 1));
        }
        out_pts[(size_t)cent * 128 + m * 32 + lane] = c[0];
    }
}

// ---------------------------------------------------------------------------
extern "C" void kernel_launch(void* const* d_in, const int* in_sizes, int n_in,
                              void* d_out, int out_size)
{
    const float* xyz    = (const float*)d_in[0];
    const float* points = (const float*)d_in[1];
    const float* W1     = (const float*)d_in[2];
    const float* b1     = (const float*)d_in[3];
    const float* W2     = (const float*)d_in[4];
    const float* b2     = (const float*)d_in[5];
    const float* W3     = (const float*)d_in[6];
    const float* b3     = (const float*)d_in[7];

    float* out = (float*)d_out;
    float* out_xyz = out;                                  // 16*1024*3
    float* out_pts = out + BB * NPT * 3;                   // 16*1024*128
    float* out_idx = out + BB * NPT * 3 + BB * NPT * 128;  // 16*1024*32

    cudaFuncSetAttribute(k_fps_pre1, cudaFuncAttributeMaxDynamicSharedMemorySize, 118784);
    cudaFuncSetAttribute(k_query,    cudaFuncAttributeMaxDynamicSharedMemorySize, 49152);
    cudaFuncSetAttribute(k_mlp,      cudaFuncAttributeMaxDynamicSharedMemorySize, 51968);

    k_fps_pre1<<<164, 512, 118784>>>(xyz, points, W1, out_xyz);
    k_query<<<256, 256, 49152>>>(xyz, out_idx);
    k_mlp<<<4096, 128, 51968>>>(W2, b2, W3, b3, W1, b1, out_pts);
}

// round 6
// speedup vs baseline: 2.1050x; 1.0351x over previous
#include <cuda_runtime.h>

#define BB 16
#define NN 4096
#define CC 64
#define NPT 1024
#define NSMP 32

typedef unsigned long long u64;

// ---------------- scratch (device globals; no allocations allowed) ----------
__device__ __align__(16) float g_pre1[BB * NN * CC];   // 16 MB: per-point layer-1 pre-activation
__device__ float g_new_xyz[BB * NPT * 3];
__device__ int   g_idx[BB * NPT * NSMP];

// ---------------- helpers ---------------------------------------------------
__device__ __forceinline__ unsigned redux_max_u32(unsigned v) {
    unsigned r;
    asm("redux.sync.max.u32 %0, %1, 0xffffffff;" : "=r"(r) : "r"(v));
    return r;
}
__device__ __forceinline__ unsigned redux_min_u32(unsigned v) {
    unsigned r;
    asm("redux.sync.min.u32 %0, %1, 0xffffffff;" : "=r"(r) : "r"(v));
    return r;
}
__device__ __forceinline__ u64 pack2(float lo, float hi) {
    u64 r;
    asm("mov.b64 %0, {%1, %2};" : "=l"(r) : "f"(lo), "f"(hi));
    return r;
}
__device__ __forceinline__ void unpack2(u64 v, float& lo, float& hi) {
    asm("mov.b64 {%0, %1}, %2;" : "=f"(lo), "=f"(hi) : "l"(v));
}
__device__ __forceinline__ u64 fma2(u64 a, u64 b, u64 c) {
    u64 r;
    asm("fma.rn.f32x2 %0, %1, %2, %3;" : "=l"(r) : "l"(a), "l"(b), "l"(c));
    return r;
}
__device__ __forceinline__ u64 add2(u64 a, u64 b) {
    u64 r;
    asm("add.rn.f32x2 %0, %1, %2;" : "=l"(r) : "l"(a), "l"(b));
    return r;
}
__device__ __forceinline__ u64 mul2(u64 a, u64 b) {
    u64 r;
    asm("mul.rn.f32x2 %0, %1, %2;" : "=l"(r) : "l"(a), "l"(b));
    return r;
}

// ---------------------------------------------------------------------------
// K1: blocks [0,16): farthest point sampling (one block per batch, 512 thr)
//     blocks [16,..): pre1 = xyz @ W1[:3] + points @ W1[3:]  (per original point)
// 116KB dyn smem per block -> exactly one block per SM (FPS isolation)
// ---------------------------------------------------------------------------
extern "C" __global__ void __launch_bounds__(512)
k_fps_pre1(const float* __restrict__ xyz, const float* __restrict__ points,
           const float* __restrict__ W1, float* __restrict__ out_xyz)
{
    extern __shared__ float sm[];
    int t = threadIdx.x;

    if (blockIdx.x < BB) {
        // ---------------- FPS ----------------
        int b = blockIdx.x;
        float* sx = sm;
        float* sy = sm + NN;
        float* sz = sm + 2 * NN;
        uint2* spair = (uint2*)(sm + 3 * NN);        // 2 buffers x 16 (wmaxbits, widx)
        int*   sfps  = (int*)(sm + 3 * NN + 64);     // 1024 fps indices

        const float* xb = xyz + (size_t)b * NN * 3;
        for (int i = t; i < NN * 3; i += 512) {
            int n = i / 3, c = i - n * 3;
            float v = xb[i];
            ((c == 0) ? sx : (c == 1) ? sy : sz)[n] = v;
        }
        __syncthreads();

        // 8 points per thread: indices t + k*512, packed in pairs (2a, 2a+1)
        float dd[8];
        u64 PX[4], PY[4], PZ[4];
        #pragma unroll
        for (int a = 0; a < 4; a++) {
            int p0 = t + (2 * a) * 512, p1 = t + (2 * a + 1) * 512;
            PX[a] = pack2(sx[p0], sx[p1]);
            PY[a] = pack2(sy[p0], sy[p1]);
            PZ[a] = pack2(sz[p0], sz[p1]);
            dd[2 * a] = 1e10f; dd[2 * a + 1] = 1e10f;
        }

        int warp = t >> 5, lane = t & 31;
        int far = 0;
        float cx = sx[0], cy = sy[0], cz = sz[0];

        for (int s = 0; s < NPT; s++) {
            if (t == 0) sfps[s] = far;   // centroid index for step s

            float ncxf = -cx, ncyf = -cy, nczf = -cz;
            u64 ncx = pack2(ncxf, ncxf);
            u64 ncy = pack2(ncyf, ncyf);
            u64 ncz = pack2(nczf, nczf);

            // packed distance, exact per-lane RN, same op order as XLA:
            // d = ((p-c).x^2 + (p-c).y^2) + (p-c).z^2   (mul then add, no fma)
            unsigned lb = 0; int li = t;
            #pragma unroll
            for (int a = 0; a < 4; a++) {
                u64 dx = add2(PX[a], ncx);
                u64 dy = add2(PY[a], ncy);
                u64 dz = add2(PZ[a], ncz);
                u64 d2 = add2(add2(mul2(dx, dx), mul2(dy, dy)), mul2(dz, dz));
                float dlo, dhi;
                unpack2(d2, dlo, dhi);
                dd[2 * a]     = fminf(dd[2 * a], dlo);
                dd[2 * a + 1] = fminf(dd[2 * a + 1], dhi);
                unsigned blo = __float_as_uint(dd[2 * a]);      // dd>=0: monotone
                unsigned bhi = __float_as_uint(dd[2 * a + 1]);
                if (a == 0) { lb = blo; li = t; }
                else if (blo > lb) { lb = blo; li = t + (2 * a) * 512; }
                if (bhi > lb) { lb = bhi; li = t + (2 * a + 1) * 512; }
            }
            // warp argmax: max bits, then min index among ties (exact first-max)
            unsigned wmax = redux_max_u32(lb);
            unsigned cand = (lb == wmax) ? (unsigned)li : 0xffffffffu;
            unsigned wbesti = redux_min_u32(cand);
            if (lane == 0) spair[(s & 1) * 16 + warp] = make_uint2(wmax, wbesti);
            __syncthreads();
            // every warp redundantly reduces the 16 warp results (lane&15 dup)
            uint2 pr = spair[(s & 1) * 16 + (lane & 15)];
            unsigned gmax = redux_max_u32(pr.x);
            unsigned c2 = (pr.x == gmax) ? pr.y : 0xffffffffu;
            far = (int)redux_min_u32(c2);
            cx = sx[far]; cy = sy[far]; cz = sz[far];
        }
        __syncthreads();

        // gather new_xyz: thread t handles centroids t and t+512
        #pragma unroll
        for (int hh = 0; hh < 2; hh++) {
            int sc = t + hh * 512;
            int fi = sfps[sc];
            int o = (b * NPT + sc) * 3;
            float nx = sx[fi], ny = sy[fi], nz = sz[fi];
            g_new_xyz[o] = nx; g_new_xyz[o + 1] = ny; g_new_xyz[o + 2] = nz;
            out_xyz[o] = nx; out_xyz[o + 1] = ny; out_xyz[o + 2] = nz;
        }
    } else {
        // ---------------- pre1 ----------------
        float* W1s = sm; // 67*64 floats
        for (int i = t; i < 67 * 64; i += 512) W1s[i] = W1[i];
        __syncthreads();
        int nb = gridDim.x - BB;
        const int total = BB * NN * CC;
        for (int e = (blockIdx.x - BB) * 512 + t; e < total; e += nb * 512) {
            int r = e >> 6;       // global point row (b*N + n)
            int d = e & 63;       // output channel
            const float* xr = xyz + (size_t)r * 3;
            float acc = fmaf(xr[2], W1s[2 * 64 + d],
                        fmaf(xr[1], W1s[1 * 64 + d], xr[0] * W1s[d]));
            const float* pr = points + (size_t)r * 64;
            #pragma unroll 8
            for (int c = 0; c < 64; c++)
                acc = fmaf(pr[c], W1s[(3 + c) * 64 + d], acc);
            g_pre1[e] = acc;
        }
    }
}

// ---------------------------------------------------------------------------
// K2: query_ball — first 32 indices (ascending) with d <= R^2, pad with first
// ---------------------------------------------------------------------------
extern "C" __global__ void __launch_bounds__(256)
k_query(const float* __restrict__ xyz, float* __restrict__ out_idx)
{
    extern __shared__ float sm[];
    float* sx = sm;
    float* sy = sm + NN;
    float* sz = sm + 2 * NN;
    int b = blockIdx.x >> 4;
    int blk = blockIdx.x & 15;

    const float* xb = xyz + (size_t)b * NN * 3;
    for (int i = threadIdx.x; i < NN * 3; i += 256) {
        int n = i / 3, c = i - n * 3;
        ((c == 0) ? sx : (c == 1) ? sy : sz)[n] = xb[i];
    }
    __syncthreads();

    int warp = threadIdx.x >> 5, lane = threadIdx.x & 31;
    const float R2 = 0.04f;  // float-rounded 0.04, matches JAX weak-typed radius^2

    for (int q = 0; q < 8; q++) {
        int s = blk * 64 + warp * 8 + q;
        int cb = b * NPT + s;
        float cx = g_new_xyz[cb * 3], cy = g_new_xyz[cb * 3 + 1], cz = g_new_xyz[cb * 3 + 2];
        int base = cb * NSMP;
        int cnt = 0, first = 0;
        for (int ch = 0; ch < NN / 32; ch++) {
            int p = ch * 32 + lane;
            float dx = __fadd_rn(sx[p], -cx);
            float dy = __fadd_rn(sy[p], -cy);
            float dz = __fadd_rn(sz[p], -cz);
            float d = __fadd_rn(__fadd_rn(__fmul_rn(dx, dx), __fmul_rn(dy, dy)),
                                __fmul_rn(dz, dz));
            bool ok = (d <= R2);
            unsigned m = __ballot_sync(0xffffffffu, ok);
            if (m) {
                if (cnt == 0) first = ch * 32 + __ffs(m) - 1;
                int pos = cnt + __popc(m & ((1u << lane) - 1u));
                if (ok && pos < NSMP) {
                    g_idx[base + pos] = p;
                    out_idx[base + pos] = (float)p;
                }
                cnt += __popc(m);
                if (cnt >= NSMP) break;
            }
        }
        if (cnt < NSMP) {
            int slot = cnt + lane;
            if (slot < NSMP) {
                g_idx[base + slot] = first;
                out_idx[base + slot] = (float)first;
            }
        }
    }
}

// ---------------------------------------------------------------------------
// K3: per-centroid MLP (64->64->128) + max over 32 samples
//     one warp per centroid, lane = sample
//     layer1 fused into layer2 loop (h produced 4-at-a-time from pipelined
//     pre1 stream) -> low regs -> 4 blocks/SM
// ---------------------------------------------------------------------------
extern "C" __global__ void __launch_bounds__(128, 4)
k_mlp(const float* __restrict__ W2, const float* __restrict__ b2,
      const float* __restrict__ W3, const float* __restrict__ b3,
      const float* __restrict__ W1, const float* __restrict__ b1,
      float* __restrict__ out_pts)
{
    extern __shared__ float sm[];
    float* W2s  = sm;            // 4096
    float* W3s  = sm + 4096;     // 8192
    float* W1x  = sm + 12288;    // 192 (first 3 rows of W1)
    float* b1s  = sm + 12480;    // 64
    float* b2s  = sm + 12544;    // 64
    float* b3s  = sm + 12608;    // 128
    float* coffs = sm + 12736;   // 4 warps * 64

    int tid = threadIdx.x;
    int warp = tid >> 5, lane = tid & 31;
    int cent = blockIdx.x * 4 + warp;          // 0 .. 16383
    int b = cent >> 10;

    // kick off the dependent index load before the smem staging barrier
    int p = g_idx[cent * NSMP + lane];

    {
        const float4* W2v = (const float4*)W2;
        float4* W2sv = (float4*)W2s;
        for (int i = tid; i < 1024; i += 128) W2sv[i] = W2v[i];
        const float4* W3v = (const float4*)W3;
        float4* W3sv = (float4*)W3s;
        for (int i = tid; i < 2048; i += 128) W3sv[i] = W3v[i];
        if (tid < 64) {
            W1x[tid] = W1[tid]; W1x[64 + tid] = W1[64 + tid]; W1x[128 + tid] = W1[128 + tid];
            b1s[tid] = b1[tid]; b2s[tid] = b2[tid];
        }
        b3s[tid] = b3[tid];
    }
    __syncthreads();

    // centroid offset: b1 - new_xyz @ W1[:3]
    float cx = g_new_xyz[cent * 3], cy = g_new_xyz[cent * 3 + 1], cz = g_new_xyz[cent * 3 + 2];
    float* co = coffs + warp * 64;
    #pragma unroll
    for (int r = 0; r < 2; r++) {
        int d = lane + r * 32;
        co[d] = b1s[d] - (cx * W1x[d] + cy * W1x[64 + d] + cz * W1x[128 + d]);
    }
    __syncwarp();

    const float4* row = (const float4*)(g_pre1 + ((size_t)(b * NN + p)) * 64);
    const float4* cov = (const float4*)co;

    // ---- layer 2 fused with layer-1 production (i ascending, bit-exact) ----
    u64 acc[32];
    {
        const u64* b2v = (const u64*)b2s;
        #pragma unroll
        for (int j = 0; j < 32; j++) acc[j] = b2v[j];
    }

    float4 buf[4];
    #pragma unroll
    for (int k = 0; k < 4; k++) buf[k] = row[k];

    #pragma unroll
    for (int g = 0; g < 4; g++) {
        float4 cur[4];
        #pragma unroll
        for (int k = 0; k < 4; k++) cur[k] = buf[k];
        if (g < 3) {
            #pragma unroll
            for (int k = 0; k < 4; k++) buf[k] = row[(g + 1) * 4 + k];
        }
        #pragma unroll
        for (int k = 0; k < 4; k++) {
            int iv = g * 4 + k;
            float4 c4 = cov[iv];
            float hs[4];
            hs[0] = fmaxf(cur[k].x + c4.x, 0.0f);
            hs[1] = fmaxf(cur[k].y + c4.y, 0.0f);
            hs[2] = fmaxf(cur[k].z + c4.z, 0.0f);
            hs[3] = fmaxf(cur[k].w + c4.w, 0.0f);
            #pragma unroll
            for (int q = 0; q < 4; q++) {
                int i = iv * 4 + q;
                u64 hh = pack2(hs[q], hs[q]);
                const ulonglong2* wr = (const ulonglong2*)(W2s + i * 64);
                #pragma unroll
                for (int jv = 0; jv < 16; jv++) {
                    ulonglong2 w = wr[jv];
                    acc[2 * jv]     = fma2(hh, w.x, acc[2 * jv]);
                    acc[2 * jv + 1] = fma2(hh, w.y, acc[2 * jv + 1]);
                }
            }
        }
    }

    float h2a[64];
    #pragma unroll
    for (int j = 0; j < 32; j++) {
        float lo, hi;
        unpack2(acc[j], lo, hi);
        h2a[2 * j]     = fmaxf(lo, 0.0f);
        h2a[2 * j + 1] = fmaxf(hi, 0.0f);
    }

    // ---- layer 3 in 4 chunks of 32 outputs + cross-lane max ----
    #pragma unroll
    for (int m = 0; m < 4; m++) {
        u64 cc[16];
        {
            const u64* b3v = (const u64*)b3s;
            #pragma unroll
            for (int j = 0; j < 16; j++) cc[j] = b3v[m * 16 + j];
        }
        #pragma unroll
        for (int i = 0; i < 64; i++) {
            u64 hh = pack2(h2a[i], h2a[i]);
            const ulonglong2* wr = (const ulonglong2*)(W3s + i * 128 + m * 32);
            #pragma unroll
            for (int jv = 0; jv < 8; jv++) {
                ulonglong2 w = wr[jv];
                cc[2 * jv]     = fma2(hh, w.x, cc[2 * jv]);
                cc[2 * jv + 1] = fma2(hh, w.y, cc[2 * jv + 1]);
            }
        }
        float c[32];
        #pragma unroll
        for (int j = 0; j < 16; j++) {
            float lo, hi;
            unpack2(cc[j], lo, hi);
            c[2 * j]     = fmaxf(lo, 0.0f);
            c[2 * j + 1] = fmaxf(hi, 0.0f);
        }

        // register-halving max reduce: lane l ends with channel m*32+l
        {
            bool up = (lane & 16) != 0;
            #pragma unroll
            for (int m2 = 0; m2 < 16; m2++) {
                float keep = up ? c[m2 + 16] : c[m2];
                float send = up ? c[m2] : c[m2 + 16];
                c[m2] = fmaxf(keep, __shfl_xor_sync(0xffffffffu, send, 16));
            }
        }
        {
            bool up = (lane & 8) != 0;
            #pragma unroll
            for (int m2 = 0; m2 < 8; m2++) {
                float keep = up ? c[m2 + 8] : c[m2];
                float send = up ? c[m2] : c[m2 + 8];
                c[m2] = fmaxf(keep, __shfl_xor_sync(0xffffffffu, send, 8));
            }
        }
        {
            bool up = (lane & 4) != 0;
            #pragma unroll
            for (int m2 = 0; m2 < 4; m2++) {
                float keep = up ? c[m2 + 4] : c[m2];
                float send = up ? c[m2] : c[m2 + 4];
                c[m2] = fmaxf(keep, __shfl_xor_sync(0xffffffffu, send, 4));
            }
        }
        {
            bool up = (lane & 2) != 0;
            #pragma unroll
            for (int m2 = 0; m2 < 2; m2++) {
                float keep = up ? c[m2 + 2] : c[m2];
                float send = up ? c[m2] : c[m2 + 2];
                c[m2] = fmaxf(keep, __shfl_xor_sync(0xffffffffu, send, 2));
            }
        }
        {
            bool up = (lane & 1) != 0;
            float keep = up ? c[1] : c[0];
            float send = up ? c[0] : c[1];
            c[0] = fmaxf(keep, __shfl_xor_sync(0xffffffffu, send, 1));
        }
        out_pts[(size_t)cent * 128 + m * 32 + lane] = c[0];
    }
}

// ---------------------------------------------------------------------------
extern "C" void kernel_launch(void* const* d_in, const int* in_sizes, int n_in,
                              void* d_out, int out_size)
{
    const float* xyz    = (const float*)d_in[0];
    const float* points = (const float*)d_in[1];
    const float* W1     = (const float*)d_in[2];
    const float* b1     = (const float*)d_in[3];
    const float* W2     = (const float*)d_in[4];
    const float* b2     = (const float*)d_in[5];
    const float* W3     = (const float*)d_in[6];
    const float* b3     = (const float*)d_in[7];

    float* out = (float*)d_out;
    float* out_xyz = out;                                  // 16*1024*3
    float* out_pts = out + BB * NPT * 3;                   // 16*1024*128
    float* out_idx = out + BB * NPT * 3 + BB * NPT * 128;  // 16*1024*32

    cudaFuncSetAttribute(k_fps_pre1, cudaFuncAttributeMaxDynamicSharedMemorySize, 118784);
    cudaFuncSetAttribute(k_query,    cudaFuncAttributeMaxDynamicSharedMemorySize, 49152);
    cudaFuncSetAttribute(k_mlp,      cudaFuncAttributeMaxDynamicSharedMemorySize, 51968);

    k_fps_pre1<<<164, 512, 118784>>>(xyz, points, W1, out_xyz);
    k_query<<<256, 256, 49152>>>(xyz, out_idx);
    k_mlp<<<4096, 128, 51968>>>(W2, b2, W3, b3, W1, b1, out_pts);
}

// round 7
// speedup vs baseline: 2.1136x; 1.0041x over previous
#include <cuda_runtime.h>

#define BB 16
#define NN 4096
#define CC 64
#define NPT 1024
#define NSMP 32

typedef unsigned long long u64;

// ---------------- scratch (device globals; no allocations allowed) ----------
__device__ __align__(16) float g_pre1[BB * NN * CC];   // 16 MB: per-point layer-1 pre-activation
__device__ float g_new_xyz[BB * NPT * 3];
__device__ int   g_idx[BB * NPT * NSMP];

// ---------------- helpers ---------------------------------------------------
__device__ __forceinline__ unsigned redux_max_u32(unsigned v) {
    unsigned r;
    asm("redux.sync.max.u32 %0, %1, 0xffffffff;" : "=r"(r) : "r"(v));
    return r;
}
__device__ __forceinline__ unsigned redux_min_u32(unsigned v) {
    unsigned r;
    asm("redux.sync.min.u32 %0, %1, 0xffffffff;" : "=r"(r) : "r"(v));
    return r;
}
__device__ __forceinline__ u64 pack2(float lo, float hi) {
    u64 r;
    asm("mov.b64 %0, {%1, %2};" : "=l"(r) : "f"(lo), "f"(hi));
    return r;
}
__device__ __forceinline__ void unpack2(u64 v, float& lo, float& hi) {
    asm("mov.b64 {%0, %1}, %2;" : "=f"(lo), "=f"(hi) : "l"(v));
}
__device__ __forceinline__ u64 fma2(u64 a, u64 b, u64 c) {
    u64 r;
    asm("fma.rn.f32x2 %0, %1, %2, %3;" : "=l"(r) : "l"(a), "l"(b), "l"(c));
    return r;
}
__device__ __forceinline__ u64 add2(u64 a, u64 b) {
    u64 r;
    asm("add.rn.f32x2 %0, %1, %2;" : "=l"(r) : "l"(a), "l"(b));
    return r;
}
__device__ __forceinline__ u64 mul2(u64 a, u64 b) {
    u64 r;
    asm("mul.rn.f32x2 %0, %1, %2;" : "=l"(r) : "l"(a), "l"(b));
    return r;
}
// in-place packed relu: unpack, clamp both halves, repack (exact per-half RN)
__device__ __forceinline__ u64 relu2(u64 v) {
    float lo, hi;
    unpack2(v, lo, hi);
    return pack2(fmaxf(lo, 0.0f), fmaxf(hi, 0.0f));
}

// ---------------------------------------------------------------------------
// K1: blocks [0,16): farthest point sampling (one block per batch, 512 thr)
//     blocks [16,..): pre1 = xyz @ W1[:3] + points @ W1[3:]  (per original point)
// 116KB dyn smem per block -> exactly one block per SM (FPS isolation)
// ---------------------------------------------------------------------------
extern "C" __global__ void __launch_bounds__(512)
k_fps_pre1(const float* __restrict__ xyz, const float* __restrict__ points,
           const float* __restrict__ W1, float* __restrict__ out_xyz)
{
    extern __shared__ float sm[];
    int t = threadIdx.x;

    if (blockIdx.x < BB) {
        // ---------------- FPS ----------------
        int b = blockIdx.x;
        float* sx = sm;
        float* sy = sm + NN;
        float* sz = sm + 2 * NN;
        uint2* spair = (uint2*)(sm + 3 * NN);        // 2 buffers x 16 (wmaxbits, widx)
        int*   sfps  = (int*)(sm + 3 * NN + 64);     // 1024 fps indices

        const float* xb = xyz + (size_t)b * NN * 3;
        for (int i = t; i < NN * 3; i += 512) {
            int n = i / 3, c = i - n * 3;
            float v = xb[i];
            ((c == 0) ? sx : (c == 1) ? sy : sz)[n] = v;
        }
        __syncthreads();

        // 8 points per thread: indices t + k*512, packed in pairs (2a, 2a+1)
        float dd[8];
        u64 PX[4], PY[4], PZ[4];
        #pragma unroll
        for (int a = 0; a < 4; a++) {
            int p0 = t + (2 * a) * 512, p1 = t + (2 * a + 1) * 512;
            PX[a] = pack2(sx[p0], sx[p1]);
            PY[a] = pack2(sy[p0], sy[p1]);
            PZ[a] = pack2(sz[p0], sz[p1]);
            dd[2 * a] = 1e10f; dd[2 * a + 1] = 1e10f;
        }

        int warp = t >> 5, lane = t & 31;
        int far = 0;
        float cx = sx[0], cy = sy[0], cz = sz[0];

        for (int s = 0; s < NPT; s++) {
            if (t == 0) sfps[s] = far;   // centroid index for step s

            float ncxf = -cx, ncyf = -cy, nczf = -cz;
            u64 ncx = pack2(ncxf, ncxf);
            u64 ncy = pack2(ncyf, ncyf);
            u64 ncz = pack2(nczf, nczf);

            // packed distance, exact per-lane RN, same op order as XLA:
            // d = ((p-c).x^2 + (p-c).y^2) + (p-c).z^2   (mul then add, no fma)
            unsigned lb = 0; int li = t;
            #pragma unroll
            for (int a = 0; a < 4; a++) {
                u64 dx = add2(PX[a], ncx);
                u64 dy = add2(PY[a], ncy);
                u64 dz = add2(PZ[a], ncz);
                u64 d2 = add2(add2(mul2(dx, dx), mul2(dy, dy)), mul2(dz, dz));
                float dlo, dhi;
                unpack2(d2, dlo, dhi);
                dd[2 * a]     = fminf(dd[2 * a], dlo);
                dd[2 * a + 1] = fminf(dd[2 * a + 1], dhi);
                unsigned blo = __float_as_uint(dd[2 * a]);      // dd>=0: monotone
                unsigned bhi = __float_as_uint(dd[2 * a + 1]);
                if (a == 0) { lb = blo; li = t; }
                else if (blo > lb) { lb = blo; li = t + (2 * a) * 512; }
                if (bhi > lb) { lb = bhi; li = t + (2 * a + 1) * 512; }
            }
            // warp argmax: max bits, then min index among ties (exact first-max)
            unsigned wmax = redux_max_u32(lb);
            unsigned cand = (lb == wmax) ? (unsigned)li : 0xffffffffu;
            unsigned wbesti = redux_min_u32(cand);
            if (lane == 0) spair[(s & 1) * 16 + warp] = make_uint2(wmax, wbesti);
            __syncthreads();
            // every warp redundantly reduces the 16 warp results (lane&15 dup)
            uint2 pr = spair[(s & 1) * 16 + (lane & 15)];
            unsigned gmax = redux_max_u32(pr.x);
            unsigned c2 = (pr.x == gmax) ? pr.y : 0xffffffffu;
            far = (int)redux_min_u32(c2);
            cx = sx[far]; cy = sy[far]; cz = sz[far];
        }
        __syncthreads();

        // gather new_xyz: thread t handles centroids t and t+512
        #pragma unroll
        for (int hh = 0; hh < 2; hh++) {
            int sc = t + hh * 512;
            int fi = sfps[sc];
            int o = (b * NPT + sc) * 3;
            float nx = sx[fi], ny = sy[fi], nz = sz[fi];
            g_new_xyz[o] = nx; g_new_xyz[o + 1] = ny; g_new_xyz[o + 2] = nz;
            out_xyz[o] = nx; out_xyz[o + 1] = ny; out_xyz[o + 2] = nz;
        }
    } else {
        // ---------------- pre1 ----------------
        float* W1s = sm; // 67*64 floats
        for (int i = t; i < 67 * 64; i += 512) W1s[i] = W1[i];
        __syncthreads();
        int nb = gridDim.x - BB;
        const int total = BB * NN * CC;
        for (int e = (blockIdx.x - BB) * 512 + t; e < total; e += nb * 512) {
            int r = e >> 6;       // global point row (b*N + n)
            int d = e & 63;       // output channel
            const float* xr = xyz + (size_t)r * 3;
            float acc = fmaf(xr[2], W1s[2 * 64 + d],
                        fmaf(xr[1], W1s[1 * 64 + d], xr[0] * W1s[d]));
            const float* pr = points + (size_t)r * 64;
            #pragma unroll 8
            for (int c = 0; c < 64; c++)
                acc = fmaf(pr[c], W1s[(3 + c) * 64 + d], acc);
            g_pre1[e] = acc;
        }
    }
}

// ---------------------------------------------------------------------------
// K2: query_ball — first 32 indices (ascending) with d <= R^2, pad with first
// ---------------------------------------------------------------------------
extern "C" __global__ void __launch_bounds__(256)
k_query(const float* __restrict__ xyz, float* __restrict__ out_idx)
{
    extern __shared__ float sm[];
    float* sx = sm;
    float* sy = sm + NN;
    float* sz = sm + 2 * NN;
    int b = blockIdx.x >> 4;
    int blk = blockIdx.x & 15;

    const float* xb = xyz + (size_t)b * NN * 3;
    for (int i = threadIdx.x; i < NN * 3; i += 256) {
        int n = i / 3, c = i - n * 3;
        ((c == 0) ? sx : (c == 1) ? sy : sz)[n] = xb[i];
    }
    __syncthreads();

    int warp = threadIdx.x >> 5, lane = threadIdx.x & 31;
    const float R2 = 0.04f;  // float-rounded 0.04, matches JAX weak-typed radius^2

    for (int q = 0; q < 8; q++) {
        int s = blk * 64 + warp * 8 + q;
        int cb = b * NPT + s;
        float cx = g_new_xyz[cb * 3], cy = g_new_xyz[cb * 3 + 1], cz = g_new_xyz[cb * 3 + 2];
        int base = cb * NSMP;
        int cnt = 0, first = 0;
        for (int ch = 0; ch < NN / 32; ch++) {
            int p = ch * 32 + lane;
            float dx = __fadd_rn(sx[p], -cx);
            float dy = __fadd_rn(sy[p], -cy);
            float dz = __fadd_rn(sz[p], -cz);
            float d = __fadd_rn(__fadd_rn(__fmul_rn(dx, dx), __fmul_rn(dy, dy)),
                                __fmul_rn(dz, dz));
            bool ok = (d <= R2);
            unsigned m = __ballot_sync(0xffffffffu, ok);
            if (m) {
                if (cnt == 0) first = ch * 32 + __ffs(m) - 1;
                int pos = cnt + __popc(m & ((1u << lane) - 1u));
                if (ok && pos < NSMP) {
                    g_idx[base + pos] = p;
                    out_idx[base + pos] = (float)p;
                }
                cnt += __popc(m);
                if (cnt >= NSMP) break;
            }
        }
        if (cnt < NSMP) {
            int slot = cnt + lane;
            if (slot < NSMP) {
                g_idx[base + slot] = first;
                out_idx[base + slot] = (float)first;
            }
        }
    }
}

// ---------------------------------------------------------------------------
// K3: per-centroid MLP (64->64->128) + max over 32 samples
//     one warp per centroid, lane = sample
//     layer1 fused into layer2 loop; h2 kept PACKED in the layer-2
//     accumulators (in-place relu) -> peak regs ~115 -> no spills @ (128,4)
// ---------------------------------------------------------------------------
extern "C" __global__ void __launch_bounds__(128, 4)
k_mlp(const float* __restrict__ W2, const float* __restrict__ b2,
      const float* __restrict__ W3, const float* __restrict__ b3,
      const float* __restrict__ W1, const float* __restrict__ b1,
      float* __restrict__ out_pts)
{
    extern __shared__ float sm[];
    float* W2s  = sm;            // 4096
    float* W3s  = sm + 4096;     // 8192
    float* W1x  = sm + 12288;    // 192 (first 3 rows of W1)
    float* b1s  = sm + 12480;    // 64
    float* b2s  = sm + 12544;    // 64
    float* b3s  = sm + 12608;    // 128
    float* coffs = sm + 12736;   // 4 warps * 64

    int tid = threadIdx.x;
    int warp = tid >> 5, lane = tid & 31;
    int cent = blockIdx.x * 4 + warp;          // 0 .. 16383
    int b = cent >> 10;

    // kick off the dependent index load before the smem staging barrier
    int p = g_idx[cent * NSMP + lane];

    {
        const float4* W2v = (const float4*)W2;
        float4* W2sv = (float4*)W2s;
        for (int i = tid; i < 1024; i += 128) W2sv[i] = W2v[i];
        const float4* W3v = (const float4*)W3;
        float4* W3sv = (float4*)W3s;
        for (int i = tid; i < 2048; i += 128) W3sv[i] = W3v[i];
        if (tid < 64) {
            W1x[tid] = W1[tid]; W1x[64 + tid] = W1[64 + tid]; W1x[128 + tid] = W1[128 + tid];
            b1s[tid] = b1[tid]; b2s[tid] = b2[tid];
        }
        b3s[tid] = b3[tid];
    }
    __syncthreads();

    // centroid offset: b1 - new_xyz @ W1[:3]
    float cx = g_new_xyz[cent * 3], cy = g_new_xyz[cent * 3 + 1], cz = g_new_xyz[cent * 3 + 2];
    float* co = coffs + warp * 64;
    #pragma unroll
    for (int r = 0; r < 2; r++) {
        int d = lane + r * 32;
        co[d] = b1s[d] - (cx * W1x[d] + cy * W1x[64 + d] + cz * W1x[128 + d]);
    }
    __syncwarp();

    const float4* row = (const float4*)(g_pre1 + ((size_t)(b * NN + p)) * 64);
    const float4* cov = (const float4*)co;

    // ---- layer 2 fused with layer-1 production (i ascending, bit-exact) ----
    u64 acc[32];
    {
        const u64* b2v = (const u64*)b2s;
        #pragma unroll
        for (int j = 0; j < 32; j++) acc[j] = b2v[j];
    }

    float4 buf[4];
    #pragma unroll
    for (int k = 0; k < 4; k++) buf[k] = row[k];

    #pragma unroll
    for (int g = 0; g < 4; g++) {
        float4 cur[4];
        #pragma unroll
        for (int k = 0; k < 4; k++) cur[k] = buf[k];
        if (g < 3) {
            #pragma unroll
            for (int k = 0; k < 4; k++) buf[k] = row[(g + 1) * 4 + k];
        }
        #pragma unroll
        for (int k = 0; k < 4; k++) {
            int iv = g * 4 + k;
            float4 c4 = cov[iv];
            float hs[4];
            hs[0] = fmaxf(cur[k].x + c4.x, 0.0f);
            hs[1] = fmaxf(cur[k].y + c4.y, 0.0f);
            hs[2] = fmaxf(cur[k].z + c4.z, 0.0f);
            hs[3] = fmaxf(cur[k].w + c4.w, 0.0f);
            #pragma unroll
            for (int q = 0; q < 4; q++) {
                int i = iv * 4 + q;
                u64 hh = pack2(hs[q], hs[q]);
                const ulonglong2* wr = (const ulonglong2*)(W2s + i * 64);
                #pragma unroll
                for (int jv = 0; jv < 16; jv++) {
                    ulonglong2 w = wr[jv];
                    acc[2 * jv]     = fma2(hh, w.x, acc[2 * jv]);
                    acc[2 * jv + 1] = fma2(hh, w.y, acc[2 * jv + 1]);
                }
            }
        }
    }

    // in-place packed relu: acc[] now holds h2 (channels 2j, 2j+1 per reg)
    #pragma unroll
    for (int j = 0; j < 32; j++) acc[j] = relu2(acc[j]);

    // ---- layer 3 in 4 chunks of 32 outputs + cross-lane max ----
    // h2 values unpacked on the fly from acc (i = 2j then 2j+1: exact order)
    #pragma unroll
    for (int m = 0; m < 4; m++) {
        u64 cc[16];
        {
            const u64* b3v = (const u64*)b3s;
            #pragma unroll
            for (int j = 0; j < 16; j++) cc[j] = b3v[m * 16 + j];
        }
        #pragma unroll
        for (int j = 0; j < 32; j++) {
            float hlo, hhi;
            unpack2(acc[j], hlo, hhi);
            u64 h0 = pack2(hlo, hlo);
            u64 h1 = pack2(hhi, hhi);
            const ulonglong2* wr0 = (const ulonglong2*)(W3s + (2 * j) * 128 + m * 32);
            const ulonglong2* wr1 = (const ulonglong2*)(W3s + (2 * j + 1) * 128 + m * 32);
            #pragma unroll
            for (int jv = 0; jv < 8; jv++) {
                ulonglong2 w = wr0[jv];
                cc[2 * jv]     = fma2(h0, w.x, cc[2 * jv]);
                cc[2 * jv + 1] = fma2(h0, w.y, cc[2 * jv + 1]);
            }
            #pragma unroll
            for (int jv = 0; jv < 8; jv++) {
                ulonglong2 w = wr1[jv];
                cc[2 * jv]     = fma2(h1, w.x, cc[2 * jv]);
                cc[2 * jv + 1] = fma2(h1, w.y, cc[2 * jv + 1]);
            }
        }
        float c[32];
        #pragma unroll
        for (int j = 0; j < 16; j++) {
            float lo, hi;
            unpack2(cc[j], lo, hi);
            c[2 * j]     = fmaxf(lo, 0.0f);
            c[2 * j + 1] = fmaxf(hi, 0.0f);
        }

        // register-halving max reduce: lane l ends with channel m*32+l
        {
            bool up = (lane & 16) != 0;
            #pragma unroll
            for (int m2 = 0; m2 < 16; m2++) {
                float keep = up ? c[m2 + 16] : c[m2];
                float send = up ? c[m2] : c[m2 + 16];
                c[m2] = fmaxf(keep, __shfl_xor_sync(0xffffffffu, send, 16));
            }
        }
        {
            bool up = (lane & 8) != 0;
            #pragma unroll
            for (int m2 = 0; m2 < 8; m2++) {
                float keep = up ? c[m2 + 8] : c[m2];
                float send = up ? c[m2] : c[m2 + 8];
                c[m2] = fmaxf(keep, __shfl_xor_sync(0xffffffffu, send, 8));
            }
        }
        {
            bool up = (lane & 4) != 0;
            #pragma unroll
            for (int m2 = 0; m2 < 4; m2++) {
                float keep = up ? c[m2 + 4] : c[m2];
                float send = up ? c[m2] : c[m2 + 4];
                c[m2] = fmaxf(keep, __shfl_xor_sync(0xffffffffu, send, 4));
            }
        }
        {
            bool up = (lane & 2) != 0;
            #pragma unroll
            for (int m2 = 0; m2 < 2; m2++) {
                float keep = up ? c[m2 + 2] : c[m2];
                float send = up ? c[m2] : c[m2 + 2];
                c[m2] = fmaxf(keep, __shfl_xor_sync(0xffffffffu, send, 2));
            }
        }
        {
            bool up = (lane & 1) != 0;
            float keep = up ? c[1] : c[0];
            float send = up ? c[0] : c[1];
            c[0] = fmaxf(keep, __shfl_xor_sync(0xffffffffu, send, 1));
        }
        out_pts[(size_t)cent * 128 + m * 32 + lane] = c[0];
    }
}

// ---------------------------------------------------------------------------
extern "C" void kernel_launch(void* const* d_in, const int* in_sizes, int n_in,
                              void* d_out, int out_size)
{
    const float* xyz    = (const float*)d_in[0];
    const float* points = (const float*)d_in[1];
    const float* W1     = (const float*)d_in[2];
    const float* b1     = (const float*)d_in[3];
    const float* W2     = (const float*)d_in[4];
    const float* b2     = (const float*)d_in[5];
    const float* W3     = (const float*)d_in[6];
    const float* b3     = (const float*)d_in[7];

    float* out = (float*)d_out;
    float* out_xyz = out;                                  // 16*1024*3
    float* out_pts = out + BB * NPT * 3;                   // 16*1024*128
    float* out_idx = out + BB * NPT * 3 + BB * NPT * 128;  // 16*1024*32

    cudaFuncSetAttribute(k_fps_pre1, cudaFuncAttributeMaxDynamicSharedMemorySize, 118784);
    cudaFuncSetAttribute(k_query,    cudaFuncAttributeMaxDynamicSharedMemorySize, 49152);
    cudaFuncSetAttribute(k_mlp,      cudaFuncAttributeMaxDynamicSharedMemorySize, 51968);

    k_fps_pre1<<<164, 512, 118784>>>(xyz, points, W1, out_xyz);
    k_query<<<256, 256, 49152>>>(xyz, out_idx);
    k_mlp<<<4096, 128, 51968>>>(W2, b2, W3, b3, W1, b1, out_pts);
}

// round 11
// speedup vs baseline: 2.2918x; 1.0843x over previous
#include <cuda_runtime.h>
#include <cuda_bf16.h>
#include <mma.h>
#include <cstdint>

using namespace nvcuda;

#define BB 16
#define NN 4096
#define CC 64
#define NPT 1024
#define NSMP 32

typedef unsigned long long u64;
typedef unsigned int u32;

// ---------------- scratch (device globals; no allocations allowed) ----------
__device__ __align__(16) float g_pre1[BB * NN * CC];   // 16 MB
__device__ float g_new_xyz[BB * NPT * 3];
__device__ int   g_idx[BB * NPT * NSMP];
// plain row-major bf16 weight images: W2 hi(0)/lo(8192), W3 hi(16384)/lo(32768)
__device__ __align__(16) unsigned char g_wimg[49152];

// ---------------- helpers ---------------------------------------------------
__device__ __forceinline__ unsigned redux_max_u32(unsigned v) {
    unsigned r; asm("redux.sync.max.u32 %0, %1, 0xffffffff;" : "=r"(r) : "r"(v)); return r;
}
__device__ __forceinline__ unsigned redux_min_u32(unsigned v) {
    unsigned r; asm("redux.sync.min.u32 %0, %1, 0xffffffff;" : "=r"(r) : "r"(v)); return r;
}
__device__ __forceinline__ u64 pack2(float lo, float hi) {
    u64 r; asm("mov.b64 %0, {%1, %2};" : "=l"(r) : "f"(lo), "f"(hi)); return r;
}
__device__ __forceinline__ void unpack2(u64 v, float& lo, float& hi) {
    asm("mov.b64 {%0, %1}, %2;" : "=f"(lo), "=f"(hi) : "l"(v));
}
__device__ __forceinline__ u64 add2(u64 a, u64 b) {
    u64 r; asm("add.rn.f32x2 %0, %1, %2;" : "=l"(r) : "l"(a), "l"(b)); return r;
}
__device__ __forceinline__ u64 mul2(u64 a, u64 b) {
    u64 r; asm("mul.rn.f32x2 %0, %1, %2;" : "=l"(r) : "l"(a), "l"(b)); return r;
}
// packed bf16x2 convert: upper half = hi_src, lower half = lo_src
__device__ __forceinline__ u32 cvt_bf16x2(float hi_src, float lo_src) {
    u32 r; asm("cvt.rn.satfinite.bf16x2.f32 %0, %1, %2;" : "=r"(r) : "f"(hi_src), "f"(lo_src)); return r;
}

// ---------------------------------------------------------------------------
// K0: prep — split W2 / W3 into bf16 hi/lo row-major images
// ---------------------------------------------------------------------------
extern "C" __global__ void k_prep(const float* __restrict__ W2, const float* __restrict__ W3)
{
    int tid = blockIdx.x * blockDim.x + threadIdx.x;
    __nv_bfloat16* w2h = (__nv_bfloat16*)(g_wimg);
    __nv_bfloat16* w2l = (__nv_bfloat16*)(g_wimg + 8192);
    __nv_bfloat16* w3h = (__nv_bfloat16*)(g_wimg + 16384);
    __nv_bfloat16* w3l = (__nv_bfloat16*)(g_wimg + 32768);
    for (int e = tid; e < 64 * 64; e += gridDim.x * blockDim.x) {
        float v = W2[e];
        __nv_bfloat16 hb = __float2bfloat16(v);
        float hf = __bfloat162float(hb);
        w2h[e] = hb;
        w2l[e] = __float2bfloat16(v - hf);
    }
    for (int e = tid; e < 64 * 128; e += gridDim.x * blockDim.x) {
        float v = W3[e];
        __nv_bfloat16 hb = __float2bfloat16(v);
        float hf = __bfloat162float(hb);
        w3h[e] = hb;
        w3l[e] = __float2bfloat16(v - hf);
    }
}

// ---------------------------------------------------------------------------
// K1: FPS (blocks [0,16)) + pre1 (rest) — unchanged (proven)
// ---------------------------------------------------------------------------
extern "C" __global__ void __launch_bounds__(512)
k_fps_pre1(const float* __restrict__ xyz, const float* __restrict__ points,
           const float* __restrict__ W1, float* __restrict__ out_xyz)
{
    extern __shared__ float sm[];
    int t = threadIdx.x;

    if (blockIdx.x < BB) {
        int b = blockIdx.x;
        float* sx = sm;
        float* sy = sm + NN;
        float* sz = sm + 2 * NN;
        uint2* spair = (uint2*)(sm + 3 * NN);
        int*   sfps  = (int*)(sm + 3 * NN + 64);

        const float* xb = xyz + (size_t)b * NN * 3;
        for (int i = t; i < NN * 3; i += 512) {
            int n = i / 3, c = i - n * 3;
            float v = xb[i];
            ((c == 0) ? sx : (c == 1) ? sy : sz)[n] = v;
        }
        __syncthreads();

        float dd[8];
        u64 PX[4], PY[4], PZ[4];
        #pragma unroll
        for (int a = 0; a < 4; a++) {
            int p0 = t + (2 * a) * 512, p1 = t + (2 * a + 1) * 512;
            PX[a] = pack2(sx[p0], sx[p1]);
            PY[a] = pack2(sy[p0], sy[p1]);
            PZ[a] = pack2(sz[p0], sz[p1]);
            dd[2 * a] = 1e10f; dd[2 * a + 1] = 1e10f;
        }

        int warp = t >> 5, lane = t & 31;
        int far = 0;
        float cx = sx[0], cy = sy[0], cz = sz[0];

        for (int s = 0; s < NPT; s++) {
            if (t == 0) sfps[s] = far;

            float ncxf = -cx, ncyf = -cy, nczf = -cz;
            u64 ncx = pack2(ncxf, ncxf);
            u64 ncy = pack2(ncyf, ncyf);
            u64 ncz = pack2(nczf, nczf);

            unsigned lb = 0; int li = t;
            #pragma unroll
            for (int a = 0; a < 4; a++) {
                u64 dx = add2(PX[a], ncx);
                u64 dy = add2(PY[a], ncy);
                u64 dz = add2(PZ[a], ncz);
                u64 d2 = add2(add2(mul2(dx, dx), mul2(dy, dy)), mul2(dz, dz));
                float dlo, dhi;
                unpack2(d2, dlo, dhi);
                dd[2 * a]     = fminf(dd[2 * a], dlo);
                dd[2 * a + 1] = fminf(dd[2 * a + 1], dhi);
                unsigned blo = __float_as_uint(dd[2 * a]);
                unsigned bhi = __float_as_uint(dd[2 * a + 1]);
                if (a == 0) { lb = blo; li = t; }
                else if (blo > lb) { lb = blo; li = t + (2 * a) * 512; }
                if (bhi > lb) { lb = bhi; li = t + (2 * a + 1) * 512; }
            }
            unsigned wmax = redux_max_u32(lb);
            unsigned cand = (lb == wmax) ? (unsigned)li : 0xffffffffu;
            unsigned wbesti = redux_min_u32(cand);
            if (lane == 0) spair[(s & 1) * 16 + warp] = make_uint2(wmax, wbesti);
            __syncthreads();
            uint2 pr = spair[(s & 1) * 16 + (lane & 15)];
            unsigned gmax = redux_max_u32(pr.x);
            unsigned c2 = (pr.x == gmax) ? pr.y : 0xffffffffu;
            far = (int)redux_min_u32(c2);
            cx = sx[far]; cy = sy[far]; cz = sz[far];
        }
        __syncthreads();

        #pragma unroll
        for (int hh = 0; hh < 2; hh++) {
            int sc = t + hh * 512;
            int fi = sfps[sc];
            int o = (b * NPT + sc) * 3;
            float nx = sx[fi], ny = sy[fi], nz = sz[fi];
            g_new_xyz[o] = nx; g_new_xyz[o + 1] = ny; g_new_xyz[o + 2] = nz;
            out_xyz[o] = nx; out_xyz[o + 1] = ny; out_xyz[o + 2] = nz;
        }
    } else {
        float* W1s = sm;
        for (int i = t; i < 67 * 64; i += 512) W1s[i] = W1[i];
        __syncthreads();
        int nb = gridDim.x - BB;
        const int total = BB * NN * CC;
        for (int e = (blockIdx.x - BB) * 512 + t; e < total; e += nb * 512) {
            int r = e >> 6;
            int d = e & 63;
            const float* xr = xyz + (size_t)r * 3;
            float acc = fmaf(xr[2], W1s[2 * 64 + d],
                        fmaf(xr[1], W1s[1 * 64 + d], xr[0] * W1s[d]));
            const float* pr = points + (size_t)r * 64;
            #pragma unroll 8
            for (int c = 0; c < 64; c++)
                acc = fmaf(pr[c], W1s[(3 + c) * 64 + d], acc);
            g_pre1[e] = acc;
        }
    }
}

// ---------------------------------------------------------------------------
// K2: query_ball — unchanged
// ---------------------------------------------------------------------------
extern "C" __global__ void __launch_bounds__(256)
k_query(const float* __restrict__ xyz, float* __restrict__ out_idx)
{
    extern __shared__ float sm[];
    float* sx = sm;
    float* sy = sm + NN;
    float* sz = sm + 2 * NN;
    int b = blockIdx.x >> 4;
    int blk = blockIdx.x & 15;

    const float* xb = xyz + (size_t)b * NN * 3;
    for (int i = threadIdx.x; i < NN * 3; i += 256) {
        int n = i / 3, c = i - n * 3;
        ((c == 0) ? sx : (c == 1) ? sy : sz)[n] = xb[i];
    }
    __syncthreads();

    int warp = threadIdx.x >> 5, lane = threadIdx.x & 31;
    const float R2 = 0.04f;

    for (int q = 0; q < 8; q++) {
        int s = blk * 64 + warp * 8 + q;
        int cb = b * NPT + s;
        float cx = g_new_xyz[cb * 3], cy = g_new_xyz[cb * 3 + 1], cz = g_new_xyz[cb * 3 + 2];
        int base = cb * NSMP;
        int cnt = 0, first = 0;
        for (int ch = 0; ch < NN / 32; ch++) {
            int p = ch * 32 + lane;
            float dx = __fadd_rn(sx[p], -cx);
            float dy = __fadd_rn(sy[p], -cy);
            float dz = __fadd_rn(sz[p], -cz);
            float d = __fadd_rn(__fadd_rn(__fmul_rn(dx, dx), __fmul_rn(dy, dy)),
                                __fmul_rn(dz, dz));
            bool ok = (d <= R2);
            unsigned m = __ballot_sync(0xffffffffu, ok);
            if (m) {
                if (cnt == 0) first = ch * 32 + __ffs(m) - 1;
                int pos = cnt + __popc(m & ((1u << lane) - 1u));
                if (ok && pos < NSMP) {
                    g_idx[base + pos] = p;
                    out_idx[base + pos] = (float)p;
                }
                cnt += __popc(m);
                if (cnt >= NSMP) break;
            }
        }
        if (cnt < NSMP) {
            int slot = cnt + lane;
            if (slot < NSMP) {
                g_idx[base + slot] = first;
                out_idx[base + slot] = (float)first;
            }
        }
    }
}

// ---------------------------------------------------------------------------
// K3: wmma (bf16 HMMA) MLP. One warp = one centroid (32 samples = 32 rows).
// 3-pass split: D = Ahi*Bhi + Ahi*Blo + Alo*Bhi, fp32 accumulate.
// SMEM layout (bytes):
//   0:      W2hi [64][64] bf16      (8192)
//   8192:   W2lo                    (8192)
//   16384:  W3hi [64][128] bf16     (16384)
//   32768:  W3lo                    (16384)
//   49152:  b2s (64f)   49408: b3s (128f)  49920: W1x (192f)  50688: b1s (64f)
//   50944:  coffs (4 warps * 64f)
//   51968:  h-stage: per warp {hi[32][72] bf16 (4608), lo (4608)} = 9216/warp
//   88832:  D-tile: per warp 32x16 float = 2048
// total 97024 -> 97536 requested; 2 blocks/SM.
// ---------------------------------------------------------------------------
#define HLD 72   // h-stage leading dim (bf16 elems)

extern "C" __global__ void __launch_bounds__(128)
k_mlp_wmma(const float* __restrict__ W1, const float* __restrict__ b1,
           const float* __restrict__ b2, const float* __restrict__ b3,
           float* __restrict__ out_pts)
{
    extern __shared__ __align__(16) char smc[];
    int tid = threadIdx.x;
    int wid = tid >> 5, lane = tid & 31;

    __nv_bfloat16* W2h = (__nv_bfloat16*)(smc);
    __nv_bfloat16* W2l = (__nv_bfloat16*)(smc + 8192);
    __nv_bfloat16* W3h = (__nv_bfloat16*)(smc + 16384);
    __nv_bfloat16* W3l = (__nv_bfloat16*)(smc + 32768);
    float* b2s  = (float*)(smc + 49152);
    float* b3s  = (float*)(smc + 49408);
    float* W1x  = (float*)(smc + 49920);
    float* b1s  = (float*)(smc + 50688);
    float* coffs = (float*)(smc + 50944);
    __nv_bfloat16* hHI = (__nv_bfloat16*)(smc + 51968 + wid * 9216);
    __nv_bfloat16* hLO = (__nv_bfloat16*)(smc + 51968 + wid * 9216 + 4608);
    float* Dt = (float*)(smc + 88832 + wid * 2048);   // [32][16]

    // ---- stage weights + small tensors ----
    {
        const float4* src = (const float4*)g_wimg;
        float4* dst = (float4*)smc;
        for (int i = tid; i < 3072; i += 128) dst[i] = src[i];
        if (tid < 64) {
            b2s[tid] = b2[tid];
            b1s[tid] = b1[tid];
            W1x[tid] = W1[tid]; W1x[64 + tid] = W1[64 + tid]; W1x[128 + tid] = W1[128 + tid];
        }
        b3s[tid] = b3[tid];
    }
    __syncthreads();

    for (int it = 0; it < 4; it++) {
        int cent = (blockIdx.x * 4 + it) * 4 + wid;
        int b = cent >> 10;

        // ---- coff = b1 - new_xyz @ W1[:3] (per warp) ----
        float ccx = g_new_xyz[cent * 3], ccy = g_new_xyz[cent * 3 + 1], ccz = g_new_xyz[cent * 3 + 2];
        float* co = coffs + wid * 64;
        #pragma unroll
        for (int r = 0; r < 2; r++) {
            int d = lane + r * 32;
            co[d] = b1s[d] - (ccx * W1x[d] + ccy * W1x[64 + d] + ccz * W1x[128 + d]);
        }
        __syncwarp();

        // ---- h1 = relu(pre1[p] + coff) -> bf16 hi/lo into h-stage (row = lane) ----
        {
            int p = g_idx[cent * NSMP + lane];
            const float4* row = (const float4*)(g_pre1 + ((size_t)(b * NN + p)) * 64);
            const float4* cov = (const float4*)co;
            u32* hr = (u32*)(hHI + lane * HLD);
            u32* lr = (u32*)(hLO + lane * HLD);
            #pragma unroll
            for (int iv = 0; iv < 16; iv++) {
                float4 v = row[iv];
                float4 c4 = cov[iv];
                float h0 = fmaxf(v.x + c4.x, 0.0f);
                float h1 = fmaxf(v.y + c4.y, 0.0f);
                float h2 = fmaxf(v.z + c4.z, 0.0f);
                float h3 = fmaxf(v.w + c4.w, 0.0f);
                u32 p0 = cvt_bf16x2(h1, h0);
                u32 p1 = cvt_bf16x2(h3, h2);
                float r0 = h0 - __uint_as_float(p0 << 16);
                float r1 = h1 - __uint_as_float(p0 & 0xffff0000u);
                float r2 = h2 - __uint_as_float(p1 << 16);
                float r3 = h3 - __uint_as_float(p1 & 0xffff0000u);
                hr[iv * 2] = p0; hr[iv * 2 + 1] = p1;
                lr[iv * 2] = cvt_bf16x2(r1, r0);
                lr[iv * 2 + 1] = cvt_bf16x2(r3, r2);
            }
        }
        __syncwarp();

        // ---- load A fragments (h1) ----
        wmma::fragment<wmma::matrix_a, 16, 16, 16, __nv_bfloat16, wmma::row_major> aH[2][4], aL[2][4];
        #pragma unroll
        for (int m = 0; m < 2; m++)
            #pragma unroll
            for (int k = 0; k < 4; k++) {
                wmma::load_matrix_sync(aH[m][k], hHI + m * 16 * HLD + k * 16, HLD);
                wmma::load_matrix_sync(aL[m][k], hLO + m * 16 * HLD + k * 16, HLD);
            }

        // ---- layer 2: acc[2][4] (32x64) = 3-pass A @ W2 ----
        wmma::fragment<wmma::accumulator, 16, 16, 16, float> acc[2][4];
        #pragma unroll
        for (int m = 0; m < 2; m++)
            #pragma unroll
            for (int n = 0; n < 4; n++)
                wmma::fill_fragment(acc[m][n], 0.0f);

        #pragma unroll
        for (int k = 0; k < 4; k++) {
            #pragma unroll
            for (int n = 0; n < 4; n++) {
                wmma::fragment<wmma::matrix_b, 16, 16, 16, __nv_bfloat16, wmma::row_major> bH, bL;
                wmma::load_matrix_sync(bH, W2h + k * 16 * 64 + n * 16, 64);
                wmma::load_matrix_sync(bL, W2l + k * 16 * 64 + n * 16, 64);
                #pragma unroll
                for (int m = 0; m < 2; m++) {
                    wmma::mma_sync(acc[m][n], aH[m][k], bH, acc[m][n]);
                    wmma::mma_sync(acc[m][n], aH[m][k], bL, acc[m][n]);
                    wmma::mma_sync(acc[m][n], aL[m][k], bH, acc[m][n]);
                }
            }
        }

        // ---- h2 = relu(acc + b2) -> bf16 hi/lo back into h-stage (per 16-col tile) ----
        {
            int c = lane & 15;
            int rbase = (lane >> 4) * 16;
            #pragma unroll
            for (int n = 0; n < 4; n++) {
                wmma::store_matrix_sync(Dt, acc[0][n], 16, wmma::mem_row_major);
                wmma::store_matrix_sync(Dt + 16 * 16, acc[1][n], 16, wmma::mem_row_major);
                __syncwarp();
                float bb = b2s[n * 16 + c];
                #pragma unroll
                for (int i = 0; i < 16; i++) {
                    int r = rbase + i;
                    float f = fmaxf(Dt[r * 16 + c] + bb, 0.0f);
                    __nv_bfloat16 hb = __float2bfloat16(f);
                    float hf = __bfloat162float(hb);
                    hHI[r * HLD + n * 16 + c] = hb;
                    hLO[r * HLD + n * 16 + c] = __float2bfloat16(f - hf);
                }
                __syncwarp();
            }
        }

        // ---- reload A fragments (h2) ----
        #pragma unroll
        for (int m = 0; m < 2; m++)
            #pragma unroll
            for (int k = 0; k < 4; k++) {
                wmma::load_matrix_sync(aH[m][k], hHI + m * 16 * HLD + k * 16, HLD);
                wmma::load_matrix_sync(aL[m][k], hLO + m * 16 * HLD + k * 16, HLD);
            }

        // ---- layer 3 in two n-halves of 64; epilogue per 16-col tile ----
        #pragma unroll
        for (int half = 0; half < 2; half++) {
            #pragma unroll
            for (int m = 0; m < 2; m++)
                #pragma unroll
                for (int n = 0; n < 4; n++)
                    wmma::fill_fragment(acc[m][n], 0.0f);

            #pragma unroll
            for (int k = 0; k < 4; k++) {
                #pragma unroll
                for (int n = 0; n < 4; n++) {
                    wmma::fragment<wmma::matrix_b, 16, 16, 16, __nv_bfloat16, wmma::row_major> bH, bL;
                    const __nv_bfloat16* bp = W3h + k * 16 * 128 + half * 64 + n * 16;
                    const __nv_bfloat16* lp = W3l + k * 16 * 128 + half * 64 + n * 16;
                    wmma::load_matrix_sync(bH, bp, 128);
                    wmma::load_matrix_sync(bL, lp, 128);
                    #pragma unroll
                    for (int m = 0; m < 2; m++) {
                        wmma::mma_sync(acc[m][n], aH[m][k], bH, acc[m][n]);
                        wmma::mma_sync(acc[m][n], aH[m][k], bL, acc[m][n]);
                        wmma::mma_sync(acc[m][n], aL[m][k], bH, acc[m][n]);
                    }
                }
            }

            // epilogue: relu(acc + b3), max over 32 rows, store 16 cols/tile
            int c = lane & 15;
            int rbase = (lane >> 4) * 16;
            #pragma unroll
            for (int n = 0; n < 4; n++) {
                wmma::store_matrix_sync(Dt, acc[0][n], 16, wmma::mem_row_major);
                wmma::store_matrix_sync(Dt + 16 * 16, acc[1][n], 16, wmma::mem_row_major);
                __syncwarp();
                float bb = b3s[half * 64 + n * 16 + c];
                float mx = 0.0f;   // relu lower bound
                #pragma unroll
                for (int i = 0; i < 16; i++)
                    mx = fmaxf(mx, Dt[(rbase + i) * 16 + c] + bb);
                mx = fmaxf(mx, __shfl_xor_sync(0xffffffffu, mx, 16));
                if (lane < 16)
                    out_pts[(size_t)cent * 128 + half * 64 + n * 16 + c] = mx;
                __syncwarp();
            }
        }
    }
}

// ---------------------------------------------------------------------------
extern "C" void kernel_launch(void* const* d_in, const int* in_sizes, int n_in,
                              void* d_out, int out_size)
{
    const float* xyz    = (const float*)d_in[0];
    const float* points = (const float*)d_in[1];
    const float* W1     = (const float*)d_in[2];
    const float* b1     = (const float*)d_in[3];
    const float* W2     = (const float*)d_in[4];
    const float* b2     = (const float*)d_in[5];
    const float* W3     = (const float*)d_in[6];
    const float* b3     = (const float*)d_in[7];

    float* out = (float*)d_out;
    float* out_xyz = out;
    float* out_pts = out + BB * NPT * 3;
    float* out_idx = out + BB * NPT * 3 + BB * NPT * 128;

    cudaFuncSetAttribute(k_fps_pre1, cudaFuncAttributeMaxDynamicSharedMemorySize, 118784);
    cudaFuncSetAttribute(k_query,    cudaFuncAttributeMaxDynamicSharedMemorySize, 49152);
    cudaFuncSetAttribute(k_mlp_wmma, cudaFuncAttributeMaxDynamicSharedMemorySize, 97536);

    k_prep<<<8, 256>>>(W2, W3);
    k_fps_pre1<<<164, 512, 118784>>>(xyz, points, W1, out_xyz);
    k_query<<<256, 256, 49152>>>(xyz, out_idx);
    k_mlp_wmma<<<1024, 128, 97536>>>(W1, b1, b2, b3, out_pts);
}

// round 13
// speedup vs baseline: 2.9000x; 1.2654x over previous
#include <cuda_runtime.h>
#include <cuda_bf16.h>
#include <mma.h>
#include <cstdint>

using namespace nvcuda;

#define BB 16
#define NN 4096
#define CC 64
#define NPT 1024
#define NSMP 32

typedef unsigned long long u64;
typedef unsigned int u32;

// padded leading dims (bf16 elems) — rotate banks across rows
#define W2LD 72
#define W3LD 136
#define HLD  72
#define DTLD 20              // f32 elems; 80B row stride
#define DT_T1 (16 * DTLD + 16)  // second m-tile offset (floats): +16 => disjoint banks
#define DT_WARP 680          // per-warp Dt floats (336 + 320 = 656, pad to 680)

// ---------------- scratch (device globals; no allocations allowed) ----------
__device__ __align__(16) float g_pre1[BB * NN * CC];   // 16 MB
__device__ float g_new_xyz[BB * NPT * 3];
__device__ int   g_idx[BB * NPT * NSMP];
// padded bf16 weight images: W2hi(0) W2lo(9216) W3hi(18432) W3lo(35840); 53248 B
__device__ __align__(16) unsigned char g_wimg[53248];

// ---------------- helpers ---------------------------------------------------
__device__ __forceinline__ unsigned redux_max_u32(unsigned v) {
    unsigned r; asm("redux.sync.max.u32 %0, %1, 0xffffffff;" : "=r"(r) : "r"(v)); return r;
}
__device__ __forceinline__ unsigned redux_min_u32(unsigned v) {
    unsigned r; asm("redux.sync.min.u32 %0, %1, 0xffffffff;" : "=r"(r) : "r"(v)); return r;
}
__device__ __forceinline__ u64 pack2(float lo, float hi) {
    u64 r; asm("mov.b64 %0, {%1, %2};" : "=l"(r) : "f"(lo), "f"(hi)); return r;
}
__device__ __forceinline__ void unpack2(u64 v, float& lo, float& hi) {
    asm("mov.b64 {%0, %1}, %2;" : "=f"(lo), "=f"(hi) : "l"(v));
}
__device__ __forceinline__ u64 add2(u64 a, u64 b) {
    u64 r; asm("add.rn.f32x2 %0, %1, %2;" : "=l"(r) : "l"(a), "l"(b)); return r;
}
__device__ __forceinline__ u64 mul2(u64 a, u64 b) {
    u64 r; asm("mul.rn.f32x2 %0, %1, %2;" : "=l"(r) : "l"(a), "l"(b)); return r;
}
// packed bf16x2 convert: upper half = hi_src, lower half = lo_src
__device__ __forceinline__ u32 cvt_bf16x2(float hi_src, float lo_src) {
    u32 r; asm("cvt.rn.satfinite.bf16x2.f32 %0, %1, %2;" : "=r"(r) : "f"(hi_src), "f"(lo_src)); return r;
}

// ---------------------------------------------------------------------------
// K0: prep — split W2 / W3 into bf16 hi/lo PADDED row-major images
// ---------------------------------------------------------------------------
extern "C" __global__ void k_prep(const float* __restrict__ W2, const float* __restrict__ W3)
{
    int tid = blockIdx.x * blockDim.x + threadIdx.x;
    __nv_bfloat16* w2h = (__nv_bfloat16*)(g_wimg);
    __nv_bfloat16* w2l = (__nv_bfloat16*)(g_wimg + 9216);
    __nv_bfloat16* w3h = (__nv_bfloat16*)(g_wimg + 18432);
    __nv_bfloat16* w3l = (__nv_bfloat16*)(g_wimg + 35840);
    for (int e = tid; e < 64 * 64; e += gridDim.x * blockDim.x) {
        int k = e >> 6, n = e & 63;
        float v = W2[e];
        __nv_bfloat16 hb = __float2bfloat16(v);
        float hf = __bfloat162float(hb);
        w2h[k * W2LD + n] = hb;
        w2l[k * W2LD + n] = __float2bfloat16(v - hf);
    }
    for (int e = tid; e < 64 * 128; e += gridDim.x * blockDim.x) {
        int k = e >> 7, n = e & 127;
        float v = W3[e];
        __nv_bfloat16 hb = __float2bfloat16(v);
        float hf = __bfloat162float(hb);
        w3h[k * W3LD + n] = hb;
        w3l[k * W3LD + n] = __float2bfloat16(v - hf);
    }
}

// ---------------------------------------------------------------------------
// K1: FPS (blocks [0,16)) + pre1 (rest) — unchanged (proven)
// ---------------------------------------------------------------------------
extern "C" __global__ void __launch_bounds__(512)
k_fps_pre1(const float* __restrict__ xyz, const float* __restrict__ points,
           const float* __restrict__ W1, float* __restrict__ out_xyz)
{
    extern __shared__ float sm[];
    int t = threadIdx.x;

    if (blockIdx.x < BB) {
        int b = blockIdx.x;
        float* sx = sm;
        float* sy = sm + NN;
        float* sz = sm + 2 * NN;
        uint2* spair = (uint2*)(sm + 3 * NN);
        int*   sfps  = (int*)(sm + 3 * NN + 64);

        const float* xb = xyz + (size_t)b * NN * 3;
        for (int i = t; i < NN * 3; i += 512) {
            int n = i / 3, c = i - n * 3;
            float v = xb[i];
            ((c == 0) ? sx : (c == 1) ? sy : sz)[n] = v;
        }
        __syncthreads();

        float dd[8];
        u64 PX[4], PY[4], PZ[4];
        #pragma unroll
        for (int a = 0; a < 4; a++) {
            int p0 = t + (2 * a) * 512, p1 = t + (2 * a + 1) * 512;
            PX[a] = pack2(sx[p0], sx[p1]);
            PY[a] = pack2(sy[p0], sy[p1]);
            PZ[a] = pack2(sz[p0], sz[p1]);
            dd[2 * a] = 1e10f; dd[2 * a + 1] = 1e10f;
        }

        int warp = t >> 5, lane = t & 31;
        int far = 0;
        float cx = sx[0], cy = sy[0], cz = sz[0];

        for (int s = 0; s < NPT; s++) {
            if (t == 0) sfps[s] = far;

            float ncxf = -cx, ncyf = -cy, nczf = -cz;
            u64 ncx = pack2(ncxf, ncxf);
            u64 ncy = pack2(ncyf, ncyf);
            u64 ncz = pack2(nczf, nczf);

            unsigned lb = 0; int li = t;
            #pragma unroll
            for (int a = 0; a < 4; a++) {
                u64 dx = add2(PX[a], ncx);
                u64 dy = add2(PY[a], ncy);
                u64 dz = add2(PZ[a], ncz);
                u64 d2 = add2(add2(mul2(dx, dx), mul2(dy, dy)), mul2(dz, dz));
                float dlo, dhi;
                unpack2(d2, dlo, dhi);
                dd[2 * a]     = fminf(dd[2 * a], dlo);
                dd[2 * a + 1] = fminf(dd[2 * a + 1], dhi);
                unsigned blo = __float_as_uint(dd[2 * a]);
                unsigned bhi = __float_as_uint(dd[2 * a + 1]);
                if (a == 0) { lb = blo; li = t; }
                else if (blo > lb) { lb = blo; li = t + (2 * a) * 512; }
                if (bhi > lb) { lb = bhi; li = t + (2 * a + 1) * 512; }
            }
            unsigned wmax = redux_max_u32(lb);
            unsigned cand = (lb == wmax) ? (unsigned)li : 0xffffffffu;
            unsigned wbesti = redux_min_u32(cand);
            if (lane == 0) spair[(s & 1) * 16 + warp] = make_uint2(wmax, wbesti);
            __syncthreads();
            uint2 pr = spair[(s & 1) * 16 + (lane & 15)];
            unsigned gmax = redux_max_u32(pr.x);
            unsigned c2 = (pr.x == gmax) ? pr.y : 0xffffffffu;
            far = (int)redux_min_u32(c2);
            cx = sx[far]; cy = sy[far]; cz = sz[far];
        }
        __syncthreads();

        #pragma unroll
        for (int hh = 0; hh < 2; hh++) {
            int sc = t + hh * 512;
            int fi = sfps[sc];
            int o = (b * NPT + sc) * 3;
            float nx = sx[fi], ny = sy[fi], nz = sz[fi];
            g_new_xyz[o] = nx; g_new_xyz[o + 1] = ny; g_new_xyz[o + 2] = nz;
            out_xyz[o] = nx; out_xyz[o + 1] = ny; out_xyz[o + 2] = nz;
        }
    } else {
        float* W1s = sm;
        for (int i = t; i < 67 * 64; i += 512) W1s[i] = W1[i];
        __syncthreads();
        int nb = gridDim.x - BB;
        const int total = BB * NN * CC;
        for (int e = (blockIdx.x - BB) * 512 + t; e < total; e += nb * 512) {
            int r = e >> 6;
            int d = e & 63;
            const float* xr = xyz + (size_t)r * 3;
            float acc = fmaf(xr[2], W1s[2 * 64 + d],
                        fmaf(xr[1], W1s[1 * 64 + d], xr[0] * W1s[d]));
            const float* pr = points + (size_t)r * 64;
            #pragma unroll 8
            for (int c = 0; c < 64; c++)
                acc = fmaf(pr[c], W1s[(3 + c) * 64 + d], acc);
            g_pre1[e] = acc;
        }
    }
}

// ---------------------------------------------------------------------------
// K2: query_ball — unchanged
// ---------------------------------------------------------------------------
extern "C" __global__ void __launch_bounds__(256)
k_query(const float* __restrict__ xyz, float* __restrict__ out_idx)
{
    extern __shared__ float sm[];
    float* sx = sm;
    float* sy = sm + NN;
    float* sz = sm + 2 * NN;
    int b = blockIdx.x >> 4;
    int blk = blockIdx.x & 15;

    const float* xb = xyz + (size_t)b * NN * 3;
    for (int i = threadIdx.x; i < NN * 3; i += 256) {
        int n = i / 3, c = i - n * 3;
        ((c == 0) ? sx : (c == 1) ? sy : sz)[n] = xb[i];
    }
    __syncthreads();

    int warp = threadIdx.x >> 5, lane = threadIdx.x & 31;
    const float R2 = 0.04f;

    for (int q = 0; q < 8; q++) {
        int s = blk * 64 + warp * 8 + q;
        int cb = b * NPT + s;
        float cx = g_new_xyz[cb * 3], cy = g_new_xyz[cb * 3 + 1], cz = g_new_xyz[cb * 3 + 2];
        int base = cb * NSMP;
        int cnt = 0, first = 0;
        for (int ch = 0; ch < NN / 32; ch++) {
            int p = ch * 32 + lane;
            float dx = __fadd_rn(sx[p], -cx);
            float dy = __fadd_rn(sy[p], -cy);
            float dz = __fadd_rn(sz[p], -cz);
            float d = __fadd_rn(__fadd_rn(__fmul_rn(dx, dx), __fmul_rn(dy, dy)),
                                __fmul_rn(dz, dz));
            bool ok = (d <= R2);
            unsigned m = __ballot_sync(0xffffffffu, ok);
            if (m) {
                if (cnt == 0) first = ch * 32 + __ffs(m) - 1;
                int pos = cnt + __popc(m & ((1u << lane) - 1u));
                if (ok && pos < NSMP) {
                    g_idx[base + pos] = p;
                    out_idx[base + pos] = (float)p;
                }
                cnt += __popc(m);
                if (cnt >= NSMP) break;
            }
        }
        if (cnt < NSMP) {
            int slot = cnt + lane;
            if (slot < NSMP) {
                g_idx[base + slot] = first;
                out_idx[base + slot] = (float)first;
            }
        }
    }
}

// ---------------------------------------------------------------------------
// K3: wmma (bf16 HMMA) MLP. One warp = one centroid (32 samples = 32 rows).
// 3-pass split: D = Ahi*Bhi + Ahi*Blo + Alo*Bhi, fp32 accumulate.
// All smem tiles use bank-rotating leading dims (W2LD=72, W3LD=136, HLD=72,
// DTLD=20 with +16 offset for m-tile 1) -> conflict-free LDSM/LDS.
// SMEM layout (bytes):
//   0:      W2hi [64][72]  (9216)       9216:  W2lo (9216)
//   18432:  W3hi [64][136] (17408)      35840: W3lo (17408)
//   53248:  b2s(256) 53504: b3s(512) 54016: W1x(768) 54784: b1s(256)
//   55040:  coffs (4*64f = 1024)
//   56064:  h-stage: per warp {hi[32][72] bf16, lo} = 9216/warp  (36864)
//   92928:  Dt: per warp DT_WARP*4 = 2720 B                      (10880)
// total 103808; 2 blocks/SM.
// ---------------------------------------------------------------------------
extern "C" __global__ void __launch_bounds__(128)
k_mlp_wmma(const float* __restrict__ W1, const float* __restrict__ b1,
           const float* __restrict__ b2, const float* __restrict__ b3,
           float* __restrict__ out_pts)
{
    extern __shared__ __align__(16) char smc[];
    int tid = threadIdx.x;
    int wid = tid >> 5, lane = tid & 31;

    __nv_bfloat16* W2h = (__nv_bfloat16*)(smc);
    __nv_bfloat16* W2l = (__nv_bfloat16*)(smc + 9216);
    __nv_bfloat16* W3h = (__nv_bfloat16*)(smc + 18432);
    __nv_bfloat16* W3l = (__nv_bfloat16*)(smc + 35840);
    float* b2s  = (float*)(smc + 53248);
    float* b3s  = (float*)(smc + 53504);
    float* W1x  = (float*)(smc + 54016);
    float* b1s  = (float*)(smc + 54784);
    float* coffs = (float*)(smc + 55040);
    __nv_bfloat16* hHI = (__nv_bfloat16*)(smc + 56064 + wid * 9216);
    __nv_bfloat16* hLO = (__nv_bfloat16*)(smc + 56064 + wid * 9216 + 4608);
    float* Dt = (float*)(smc + 92928 + wid * (DT_WARP * 4));

    // ---- stage weights + small tensors ----
    {
        const float4* src = (const float4*)g_wimg;
        float4* dst = (float4*)smc;
        for (int i = tid; i < 3328; i += 128) dst[i] = src[i];
        if (tid < 64) {
            b2s[tid] = b2[tid];
            b1s[tid] = b1[tid];
            W1x[tid] = W1[tid]; W1x[64 + tid] = W1[64 + tid]; W1x[128 + tid] = W1[128 + tid];
        }
        b3s[tid] = b3[tid];
    }
    __syncthreads();

    for (int it = 0; it < 4; it++) {
        int cent = (blockIdx.x * 4 + it) * 4 + wid;
        int b = cent >> 10;

        // ---- coff = b1 - new_xyz @ W1[:3] (per warp) ----
        float ccx = g_new_xyz[cent * 3], ccy = g_new_xyz[cent * 3 + 1], ccz = g_new_xyz[cent * 3 + 2];
        float* co = coffs + wid * 64;
        #pragma unroll
        for (int r = 0; r < 2; r++) {
            int d = lane + r * 32;
            co[d] = b1s[d] - (ccx * W1x[d] + ccy * W1x[64 + d] + ccz * W1x[128 + d]);
        }
        __syncwarp();

        // ---- h1 = relu(pre1[p] + coff) -> bf16 hi/lo into h-stage (row = lane) ----
        {
            int p = g_idx[cent * NSMP + lane];
            const float4* row = (const float4*)(g_pre1 + ((size_t)(b * NN + p)) * 64);
            const float4* cov = (const float4*)co;
            u32* hr = (u32*)(hHI + lane * HLD);
            u32* lr = (u32*)(hLO + lane * HLD);
            #pragma unroll
            for (int iv = 0; iv < 16; iv++) {
                float4 v = row[iv];
                float4 c4 = cov[iv];
                float h0 = fmaxf(v.x + c4.x, 0.0f);
                float h1 = fmaxf(v.y + c4.y, 0.0f);
                float h2 = fmaxf(v.z + c4.z, 0.0f);
                float h3 = fmaxf(v.w + c4.w, 0.0f);
                u32 p0 = cvt_bf16x2(h1, h0);
                u32 p1 = cvt_bf16x2(h3, h2);
                float r0 = h0 - __uint_as_float(p0 << 16);
                float r1 = h1 - __uint_as_float(p0 & 0xffff0000u);
                float r2 = h2 - __uint_as_float(p1 << 16);
                float r3 = h3 - __uint_as_float(p1 & 0xffff0000u);
                hr[iv * 2] = p0; hr[iv * 2 + 1] = p1;
                lr[iv * 2] = cvt_bf16x2(r1, r0);
                lr[iv * 2 + 1] = cvt_bf16x2(r3, r2);
            }
        }
        __syncwarp();

        // ---- load A fragments (h1) ----
        wmma::fragment<wmma::matrix_a, 16, 16, 16, __nv_bfloat16, wmma::row_major> aH[2][4], aL[2][4];
        #pragma unroll
        for (int m = 0; m < 2; m++)
            #pragma unroll
            for (int k = 0; k < 4; k++) {
                wmma::load_matrix_sync(aH[m][k], hHI + m * 16 * HLD + k * 16, HLD);
                wmma::load_matrix_sync(aL[m][k], hLO + m * 16 * HLD + k * 16, HLD);
            }

        // ---- layer 2: acc[2][4] (32x64) = 3-pass A @ W2 ----
        wmma::fragment<wmma::accumulator, 16, 16, 16, float> acc[2][4];
        #pragma unroll
        for (int m = 0; m < 2; m++)
            #pragma unroll
            for (int n = 0; n < 4; n++)
                wmma::fill_fragment(acc[m][n], 0.0f);

        #pragma unroll
        for (int k = 0; k < 4; k++) {
            #pragma unroll
            for (int n = 0; n < 4; n++) {
                wmma::fragment<wmma::matrix_b, 16, 16, 16, __nv_bfloat16, wmma::row_major> bH, bL;
                wmma::load_matrix_sync(bH, W2h + k * 16 * W2LD + n * 16, W2LD);
                wmma::load_matrix_sync(bL, W2l + k * 16 * W2LD + n * 16, W2LD);
                #pragma unroll
                for (int m = 0; m < 2; m++) {
                    wmma::mma_sync(acc[m][n], aH[m][k], bH, acc[m][n]);
                    wmma::mma_sync(acc[m][n], aH[m][k], bL, acc[m][n]);
                    wmma::mma_sync(acc[m][n], aL[m][k], bH, acc[m][n]);
                }
            }
        }

        // ---- h2 = relu(acc + b2) -> bf16 hi/lo back into h-stage (per 16-col tile) ----
        {
            int c = lane & 15;
            int rbase = (lane >> 4) * 16;
            int dtoff = (lane >> 4) * DT_T1;   // lanes 16-31 read the offset tile
            #pragma unroll
            for (int n = 0; n < 4; n++) {
                wmma::store_matrix_sync(Dt, acc[0][n], DTLD, wmma::mem_row_major);
                wmma::store_matrix_sync(Dt + DT_T1, acc[1][n], DTLD, wmma::mem_row_major);
                __syncwarp();
                float bb = b2s[n * 16 + c];
                #pragma unroll
                for (int i = 0; i < 16; i++) {
                    int r = rbase + i;
                    float f = fmaxf(Dt[dtoff + i * DTLD + c] + bb, 0.0f);
                    __nv_bfloat16 hb = __float2bfloat16(f);
                    float hf = __bfloat162float(hb);
                    hHI[r * HLD + n * 16 + c] = hb;
                    hLO[r * HLD + n * 16 + c] = __float2bfloat16(f - hf);
                }
                __syncwarp();
            }
        }

        // ---- reload A fragments (h2) ----
        #pragma unroll
        for (int m = 0; m < 2; m++)
            #pragma unroll
            for (int k = 0; k < 4; k++) {
                wmma::load_matrix_sync(aH[m][k], hHI + m * 16 * HLD + k * 16, HLD);
                wmma::load_matrix_sync(aL[m][k], hLO + m * 16 * HLD + k * 16, HLD);
            }

        // ---- layer 3 in two n-halves of 64; epilogue per 16-col tile ----
        #pragma unroll
        for (int half = 0; half < 2; half++) {
            #pragma unroll
            for (int m = 0; m < 2; m++)
                #pragma unroll
                for (int n = 0; n < 4; n++)
                    wmma::fill_fragment(acc[m][n], 0.0f);

            #pragma unroll
            for (int k = 0; k < 4; k++) {
                #pragma unroll
                for (int n = 0; n < 4; n++) {
                    wmma::fragment<wmma::matrix_b, 16, 16, 16, __nv_bfloat16, wmma::row_major> bH, bL;
                    const __nv_bfloat16* bp = W3h + k * 16 * W3LD + half * 64 + n * 16;
                    const __nv_bfloat16* lp = W3l + k * 16 * W3LD + half * 64 + n * 16;
                    wmma::load_matrix_sync(bH, bp, W3LD);
                    wmma::load_matrix_sync(bL, lp, W3LD);
                    #pragma unroll
                    for (int m = 0; m < 2; m++) {
                        wmma::mma_sync(acc[m][n], aH[m][k], bH, acc[m][n]);
                        wmma::mma_sync(acc[m][n], aH[m][k], bL, acc[m][n]);
                        wmma::mma_sync(acc[m][n], aL[m][k], bH, acc[m][n]);
                    }
                }
            }

            // epilogue: relu(acc + b3), max over 32 rows, store 16 cols/tile
            int c = lane & 15;
            int dtoff = (lane >> 4) * DT_T1;
            #pragma unroll
            for (int n = 0; n < 4; n++) {
                wmma::store_matrix_sync(Dt, acc[0][n], DTLD, wmma::mem_row_major);
                wmma::store_matrix_sync(Dt + DT_T1, acc[1][n], DTLD, wmma::mem_row_major);
                __syncwarp();
                float bb = b3s[half * 64 + n * 16 + c];
                float mx = 0.0f;   // relu lower bound
                #pragma unroll
                for (int i = 0; i < 16; i++)
                    mx = fmaxf(mx, Dt[dtoff + i * DTLD + c] + bb);
                mx = fmaxf(mx, __shfl_xor_sync(0xffffffffu, mx, 16));
                if (lane < 16)
                    out_pts[(size_t)cent * 128 + half * 64 + n * 16 + c] = mx;
                __syncwarp();
            }
        }
    }
}

// ---------------------------------------------------------------------------
extern "C" void kernel_launch(void* const* d_in, const int* in_sizes, int n_in,
                              void* d_out, int out_size)
{
    const float* xyz    = (const float*)d_in[0];
    const float* points = (const float*)d_in[1];
    const float* W1     = (const float*)d_in[2];
    const float* b1     = (const float*)d_in[3];
    const float* W2     = (const float*)d_in[4];
    const float* b2     = (const float*)d_in[5];
    const float* W3     = (const float*)d_in[6];
    const float* b3     = (const float*)d_in[7];

    float* out = (float*)d_out;
    float* out_xyz = out;
    float* out_pts = out + BB * NPT * 3;
    float* out_idx = out + BB * NPT * 3 + BB * NPT * 128;

    cudaFuncSetAttribute(k_fps_pre1, cudaFuncAttributeMaxDynamicSharedMemorySize, 118784);
    cudaFuncSetAttribute(k_query,    cudaFuncAttributeMaxDynamicSharedMemorySize, 49152);
    cudaFuncSetAttribute(k_mlp_wmma, cudaFuncAttributeMaxDynamicSharedMemorySize, 103808);

    k_prep<<<8, 256>>>(W2, W3);
    k_fps_pre1<<<164, 512, 118784>>>(xyz, points, W1, out_xyz);
    k_query<<<256, 256, 49152>>>(xyz, out_idx);
    k_mlp_wmma<<<1024, 128, 103808>>>(W1, b1, b2, b3, out_pts);
}

// round 14
// speedup vs baseline: 3.4190x; 1.1790x over previous
#include <cuda_runtime.h>
#include <cuda_bf16.h>
#include <cstdint>

#define BB 16
#define NN 4096
#define CC 64
#define NPT 1024
#define NSMP 32

typedef unsigned long long u64;
typedef unsigned int u32;

#define WKLD 72   // K-major weight image leading dim (bf16 elems): conflict-free

// ---------------- scratch (device globals; no allocations allowed) ----------
__device__ __align__(16) float g_pre1[BB * NN * CC];   // 16 MB
__device__ float g_new_xyz[BB * NPT * 3];
__device__ int   g_idx[BB * NPT * NSMP];
// K-major padded bf16 weights: W2T hi(0) lo(9216); W3T hi(18432) lo(36864)
__device__ __align__(16) unsigned char g_wimg[55296];

// ---------------- helpers ---------------------------------------------------
__device__ __forceinline__ unsigned redux_max_u32(unsigned v) {
    unsigned r; asm("redux.sync.max.u32 %0, %1, 0xffffffff;" : "=r"(r) : "r"(v)); return r;
}
__device__ __forceinline__ unsigned redux_min_u32(unsigned v) {
    unsigned r; asm("redux.sync.min.u32 %0, %1, 0xffffffff;" : "=r"(r) : "r"(v)); return r;
}
__device__ __forceinline__ u64 pack2(float lo, float hi) {
    u64 r; asm("mov.b64 %0, {%1, %2};" : "=l"(r) : "f"(lo), "f"(hi)); return r;
}
__device__ __forceinline__ void unpack2(u64 v, float& lo, float& hi) {
    asm("mov.b64 {%0, %1}, %2;" : "=f"(lo), "=f"(hi) : "l"(v));
}
__device__ __forceinline__ u64 add2(u64 a, u64 b) {
    u64 r; asm("add.rn.f32x2 %0, %1, %2;" : "=l"(r) : "l"(a), "l"(b)); return r;
}
__device__ __forceinline__ u64 mul2(u64 a, u64 b) {
    u64 r; asm("mul.rn.f32x2 %0, %1, %2;" : "=l"(r) : "l"(a), "l"(b)); return r;
}
// packed bf16x2: first arg -> upper 16 bits, second -> lower
__device__ __forceinline__ u32 cvt_bf16x2(float hi_src, float lo_src) {
    u32 r; asm("cvt.rn.satfinite.bf16x2.f32 %0, %1, %2;" : "=r"(r) : "f"(hi_src), "f"(lo_src)); return r;
}
// mma.m16n8k16 row.col bf16 -> f32, D += A*B
__device__ __forceinline__ void mma16816(float* c, const u32* a, u32 b0, u32 b1) {
    asm volatile(
        "mma.sync.aligned.m16n8k16.row.col.f32.bf16.bf16.f32 "
        "{%0,%1,%2,%3}, {%4,%5,%6,%7}, {%8,%9}, {%0,%1,%2,%3};"
        : "+f"(c[0]), "+f"(c[1]), "+f"(c[2]), "+f"(c[3])
        : "r"(a[0]), "r"(a[1]), "r"(a[2]), "r"(a[3]), "r"(b0), "r"(b1));
}
// split f: hi = bf16(f) in given half; returns lo residual pair packed
__device__ __forceinline__ float low_of(u32 hi)  { return __uint_as_float(hi << 16); }
__device__ __forceinline__ float high_of(u32 hi) { return __uint_as_float(hi & 0xffff0000u); }

// ---------------------------------------------------------------------------
// K0: prep — W2^T / W3^T (K-major rows, padded WKLD) split into bf16 hi/lo
// ---------------------------------------------------------------------------
extern "C" __global__ void k_prep(const float* __restrict__ W2, const float* __restrict__ W3)
{
    int tid = blockIdx.x * blockDim.x + threadIdx.x;
    __nv_bfloat16* w2h = (__nv_bfloat16*)(g_wimg);
    __nv_bfloat16* w2l = (__nv_bfloat16*)(g_wimg + 9216);
    __nv_bfloat16* w3h = (__nv_bfloat16*)(g_wimg + 18432);
    __nv_bfloat16* w3l = (__nv_bfloat16*)(g_wimg + 36864);
    for (int e = tid; e < 64 * 64; e += gridDim.x * blockDim.x) {
        int k = e >> 6, n = e & 63;
        float v = W2[e];                       // W2[k][n]
        __nv_bfloat16 hb = __float2bfloat16(v);
        float hf = __bfloat162float(hb);
        w2h[n * WKLD + k] = hb;
        w2l[n * WKLD + k] = __float2bfloat16(v - hf);
    }
    for (int e = tid; e < 64 * 128; e += gridDim.x * blockDim.x) {
        int k = e >> 7, n = e & 127;
        float v = W3[e];                       // W3[k][n]
        __nv_bfloat16 hb = __float2bfloat16(v);
        float hf = __bfloat162float(hb);
        w3h[n * WKLD + k] = hb;
        w3l[n * WKLD + k] = __float2bfloat16(v - hf);
    }
}

// ---------------------------------------------------------------------------
// K1: FPS (blocks [0,16)) + pre1 (rest) — unchanged (proven)
// ---------------------------------------------------------------------------
extern "C" __global__ void __launch_bounds__(512)
k_fps_pre1(const float* __restrict__ xyz, const float* __restrict__ points,
           const float* __restrict__ W1, float* __restrict__ out_xyz)
{
    extern __shared__ float sm[];
    int t = threadIdx.x;

    if (blockIdx.x < BB) {
        int b = blockIdx.x;
        float* sx = sm;
        float* sy = sm + NN;
        float* sz = sm + 2 * NN;
        uint2* spair = (uint2*)(sm + 3 * NN);
        int*   sfps  = (int*)(sm + 3 * NN + 64);

        const float* xb = xyz + (size_t)b * NN * 3;
        for (int i = t; i < NN * 3; i += 512) {
            int n = i / 3, c = i - n * 3;
            float v = xb[i];
            ((c == 0) ? sx : (c == 1) ? sy : sz)[n] = v;
        }
        __syncthreads();

        float dd[8];
        u64 PX[4], PY[4], PZ[4];
        #pragma unroll
        for (int a = 0; a < 4; a++) {
            int p0 = t + (2 * a) * 512, p1 = t + (2 * a + 1) * 512;
            PX[a] = pack2(sx[p0], sx[p1]);
            PY[a] = pack2(sy[p0], sy[p1]);
            PZ[a] = pack2(sz[p0], sz[p1]);
            dd[2 * a] = 1e10f; dd[2 * a + 1] = 1e10f;
        }

        int warp = t >> 5, lane = t & 31;
        int far = 0;
        float cx = sx[0], cy = sy[0], cz = sz[0];

        for (int s = 0; s < NPT; s++) {
            if (t == 0) sfps[s] = far;

            float ncxf = -cx, ncyf = -cy, nczf = -cz;
            u64 ncx = pack2(ncxf, ncxf);
            u64 ncy = pack2(ncyf, ncyf);
            u64 ncz = pack2(nczf, nczf);

            unsigned lb = 0; int li = t;
            #pragma unroll
            for (int a = 0; a < 4; a++) {
                u64 dx = add2(PX[a], ncx);
                u64 dy = add2(PY[a], ncy);
                u64 dz = add2(PZ[a], ncz);
                u64 d2 = add2(add2(mul2(dx, dx), mul2(dy, dy)), mul2(dz, dz));
                float dlo, dhi;
                unpack2(d2, dlo, dhi);
                dd[2 * a]     = fminf(dd[2 * a], dlo);
                dd[2 * a + 1] = fminf(dd[2 * a + 1], dhi);
                unsigned blo = __float_as_uint(dd[2 * a]);
                unsigned bhi = __float_as_uint(dd[2 * a + 1]);
                if (a == 0) { lb = blo; li = t; }
                else if (blo > lb) { lb = blo; li = t + (2 * a) * 512; }
                if (bhi > lb) { lb = bhi; li = t + (2 * a + 1) * 512; }
            }
            unsigned wmax = redux_max_u32(lb);
            unsigned cand = (lb == wmax) ? (unsigned)li : 0xffffffffu;
            unsigned wbesti = redux_min_u32(cand);
            if (lane == 0) spair[(s & 1) * 16 + warp] = make_uint2(wmax, wbesti);
            __syncthreads();
            uint2 pr = spair[(s & 1) * 16 + (lane & 15)];
            unsigned gmax = redux_max_u32(pr.x);
            unsigned c2 = (pr.x == gmax) ? pr.y : 0xffffffffu;
            far = (int)redux_min_u32(c2);
            cx = sx[far]; cy = sy[far]; cz = sz[far];
        }
        __syncthreads();

        #pragma unroll
        for (int hh = 0; hh < 2; hh++) {
            int sc = t + hh * 512;
            int fi = sfps[sc];
            int o = (b * NPT + sc) * 3;
            float nx = sx[fi], ny = sy[fi], nz = sz[fi];
            g_new_xyz[o] = nx; g_new_xyz[o + 1] = ny; g_new_xyz[o + 2] = nz;
            out_xyz[o] = nx; out_xyz[o + 1] = ny; out_xyz[o + 2] = nz;
        }
    } else {
        float* W1s = sm;
        for (int i = t; i < 67 * 64; i += 512) W1s[i] = W1[i];
        __syncthreads();
        int nb = gridDim.x - BB;
        const int total = BB * NN * CC;
        for (int e = (blockIdx.x - BB) * 512 + t; e < total; e += nb * 512) {
            int r = e >> 6;
            int d = e & 63;
            const float* xr = xyz + (size_t)r * 3;
            float acc = fmaf(xr[2], W1s[2 * 64 + d],
                        fmaf(xr[1], W1s[1 * 64 + d], xr[0] * W1s[d]));
            const float* pr = points + (size_t)r * 64;
            #pragma unroll 8
            for (int c = 0; c < 64; c++)
                acc = fmaf(pr[c], W1s[(3 + c) * 64 + d], acc);
            g_pre1[e] = acc;
        }
    }
}

// ---------------------------------------------------------------------------
// K2: query_ball — unchanged
// ---------------------------------------------------------------------------
extern "C" __global__ void __launch_bounds__(256)
k_query(const float* __restrict__ xyz, float* __restrict__ out_idx)
{
    extern __shared__ float sm[];
    float* sx = sm;
    float* sy = sm + NN;
    float* sz = sm + 2 * NN;
    int b = blockIdx.x >> 4;
    int blk = blockIdx.x & 15;

    const float* xb = xyz + (size_t)b * NN * 3;
    for (int i = threadIdx.x; i < NN * 3; i += 256) {
        int n = i / 3, c = i - n * 3;
        ((c == 0) ? sx : (c == 1) ? sy : sz)[n] = xb[i];
    }
    __syncthreads();

    int warp = threadIdx.x >> 5, lane = threadIdx.x & 31;
    const float R2 = 0.04f;

    for (int q = 0; q < 8; q++) {
        int s = blk * 64 + warp * 8 + q;
        int cb = b * NPT + s;
        float cx = g_new_xyz[cb * 3], cy = g_new_xyz[cb * 3 + 1], cz = g_new_xyz[cb * 3 + 2];
        int base = cb * NSMP;
        int cnt = 0, first = 0;
        for (int ch = 0; ch < NN / 32; ch++) {
            int p = ch * 32 + lane;
            float dx = __fadd_rn(sx[p], -cx);
            float dy = __fadd_rn(sy[p], -cy);
            float dz = __fadd_rn(sz[p], -cz);
            float d = __fadd_rn(__fadd_rn(__fmul_rn(dx, dx), __fmul_rn(dy, dy)),
                                __fmul_rn(dz, dz));
            bool ok = (d <= R2);
            unsigned m = __ballot_sync(0xffffffffu, ok);
            if (m) {
                if (cnt == 0) first = ch * 32 + __ffs(m) - 1;
                int pos = cnt + __popc(m & ((1u << lane) - 1u));
                if (ok && pos < NSMP) {
                    g_idx[base + pos] = p;
                    out_idx[base + pos] = (float)p;
                }
                cnt += __popc(m);
                if (cnt >= NSMP) break;
            }
        }
        if (cnt < NSMP) {
            int slot = cnt + lane;
            if (slot < NSMP) {
                g_idx[base + slot] = first;
                out_idx[base + slot] = (float)first;
            }
        }
    }
}

// ---------------------------------------------------------------------------
// K3: raw mma.m16n8k16 MLP, fragment-chained (no h smem, no Dt).
// One warp = one centroid; M=32 rows (2 m-tiles), layer2 N=64, layer3 N=128.
// 3-pass hi/lo split: D = Ah*Bh + Ah*Bl + Al*Bh (fp32 accum).
// A1 loads straight from g_pre1 (rows shfl-broadcast); h2 = relu(acc2+b2)
// converted in-registers to layer3 A fragments (PTX layout identity).
// SMEM: weights 55296 + b2(256) b3(512) W1x(768) b1(256) coffs(1024) = 58112.
// ---------------------------------------------------------------------------
extern "C" __global__ void __launch_bounds__(128)
k_mlp_mma(const float* __restrict__ W1, const float* __restrict__ b1,
          const float* __restrict__ b2, const float* __restrict__ b3,
          float* __restrict__ out_pts)
{
    extern __shared__ __align__(16) char smc[];
    int tid = threadIdx.x;
    int wid = tid >> 5, lane = tid & 31;
    int gid = lane >> 2, tidg = lane & 3;

    __nv_bfloat16* w2h = (__nv_bfloat16*)(smc);
    __nv_bfloat16* w2l = (__nv_bfloat16*)(smc + 9216);
    __nv_bfloat16* w3h = (__nv_bfloat16*)(smc + 18432);
    __nv_bfloat16* w3l = (__nv_bfloat16*)(smc + 36864);
    float* b2s  = (float*)(smc + 55296);
    float* b3s  = (float*)(smc + 55552);
    float* W1x  = (float*)(smc + 56064);
    float* b1s  = (float*)(smc + 56832);
    float* coffs = (float*)(smc + 57088);

    // ---- stage weights + small tensors ----
    {
        const float4* src = (const float4*)g_wimg;
        float4* dst = (float4*)smc;
        for (int i = tid; i < 3456; i += 128) dst[i] = src[i];
        if (tid < 64) {
            b2s[tid] = b2[tid];
            b1s[tid] = b1[tid];
            W1x[tid] = W1[tid]; W1x[64 + tid] = W1[64 + tid]; W1x[128 + tid] = W1[128 + tid];
        }
        b3s[tid] = b3[tid];
    }
    __syncthreads();

    for (int it = 0; it < 4; it++) {
        int cent = (blockIdx.x * 4 + it) * 4 + wid;
        int b = cent >> 10;

        // ---- coff = b1 - new_xyz @ W1[:3] (per warp) ----
        float ccx = g_new_xyz[cent * 3], ccy = g_new_xyz[cent * 3 + 1], ccz = g_new_xyz[cent * 3 + 2];
        float* co = coffs + wid * 64;
        #pragma unroll
        for (int r = 0; r < 2; r++) {
            int d = lane + r * 32;
            co[d] = b1s[d] - (ccx * W1x[d] + ccy * W1x[64 + d] + ccz * W1x[128 + d]);
        }
        __syncwarp();

        // ---- row pointers: sample row j needed by this lane = gid + 8j ----
        int p = g_idx[cent * NSMP + lane];
        const float* rowp[4];
        #pragma unroll
        for (int j = 0; j < 4; j++) {
            int pj = __shfl_sync(0xffffffffu, p, gid + 8 * j);
            rowp[j] = g_pre1 + ((size_t)(b * NN + pj)) * 64;
        }

        // ---- A1 fragments straight from gmem: h1 = relu(pre1 + co), split ----
        // frag reg r: 0:(row lo,colA) 1:(row hi,colA) 2:(row lo,colB) 3:(row hi,colB)
        u32 a1H[2][4][4], a1L[2][4][4];
        #pragma unroll
        for (int mt = 0; mt < 2; mt++) {
            #pragma unroll
            for (int kb = 0; kb < 4; kb++) {
                int cA = 2 * tidg + 16 * kb;
                float2 coA = *(float2*)&co[cA];
                float2 coB = *(float2*)&co[cA + 8];
                #pragma unroll
                for (int rr = 0; rr < 4; rr++) {
                    const float* rp = rowp[mt * 2 + (rr & 1)];
                    int col = cA + ((rr >> 1) ? 8 : 0);
                    float2 cv = (rr >> 1) ? coB : coA;
                    float2 v = *(const float2*)(rp + col);
                    float h0 = fmaxf(v.x + cv.x, 0.0f);
                    float h1 = fmaxf(v.y + cv.y, 0.0f);
                    u32 hi = cvt_bf16x2(h1, h0);
                    a1H[mt][kb][rr] = hi;
                    a1L[mt][kb][rr] = cvt_bf16x2(h1 - high_of(hi), h0 - low_of(hi));
                }
            }
        }

        // ---- layer 2: acc2[2][8] (32x64) ----
        float acc2[2][8][4];
        #pragma unroll
        for (int mt = 0; mt < 2; mt++)
            #pragma unroll
            for (int nt = 0; nt < 8; nt++)
                #pragma unroll
                for (int r = 0; r < 4; r++) acc2[mt][nt][r] = 0.0f;

        #pragma unroll
        for (int kb = 0; kb < 4; kb++) {
            #pragma unroll
            for (int nt = 0; nt < 8; nt++) {
                int off = (8 * nt + gid) * WKLD + 2 * tidg + 16 * kb;
                u32 bh0 = *(const u32*)(w2h + off);
                u32 bh1 = *(const u32*)(w2h + off + 8);
                u32 bl0 = *(const u32*)(w2l + off);
                u32 bl1 = *(const u32*)(w2l + off + 8);
                #pragma unroll
                for (int mt = 0; mt < 2; mt++) {
                    mma16816(acc2[mt][nt], a1H[mt][kb], bh0, bh1);
                    mma16816(acc2[mt][nt], a1H[mt][kb], bl0, bl1);
                    mma16816(acc2[mt][nt], a1L[mt][kb], bh0, bh1);
                }
            }
        }

        // ---- h2 = relu(acc2 + b2) -> layer3 A fragments (in registers) ----
        // a3[mt][kb3]: reg0 <- acc2[mt][2kb3].c0c1, reg1 <- .c2c3,
        //              reg2 <- acc2[mt][2kb3+1].c0c1, reg3 <- .c2c3
        u32 a3H[2][4][4], a3L[2][4][4];
        #pragma unroll
        for (int mt = 0; mt < 2; mt++) {
            #pragma unroll
            for (int kb = 0; kb < 4; kb++) {
                #pragma unroll
                for (int half = 0; half < 2; half++) {
                    int nt = 2 * kb + half;
                    float2 bb = *(float2*)&b2s[8 * nt + 2 * tidg];
                    #pragma unroll
                    for (int rp = 0; rp < 2; rp++) {   // rp0: rows gid.. (c0,c1); rp1: rows gid+8 (c2,c3)
                        float h0 = fmaxf(acc2[mt][nt][2 * rp]     + bb.x, 0.0f);
                        float h1 = fmaxf(acc2[mt][nt][2 * rp + 1] + bb.y, 0.0f);
                        u32 hi = cvt_bf16x2(h1, h0);
                        int r = half * 2 + rp;
                        a3H[mt][kb][r] = hi;
                        a3L[mt][kb][r] = cvt_bf16x2(h1 - high_of(hi), h0 - low_of(hi));
                    }
                }
            }
        }

        // ---- layer 3 in 2 halves of N=64; epilogue per n-tile ----
        #pragma unroll
        for (int half = 0; half < 2; half++) {
            float acc3[2][8][4];
            #pragma unroll
            for (int mt = 0; mt < 2; mt++)
                #pragma unroll
                for (int nt = 0; nt < 8; nt++)
                    #pragma unroll
                    for (int r = 0; r < 4; r++) acc3[mt][nt][r] = 0.0f;

            #pragma unroll
            for (int kb = 0; kb < 4; kb++) {
                #pragma unroll
                for (int nt = 0; nt < 8; nt++) {
                    int off = (64 * half + 8 * nt + gid) * WKLD + 2 * tidg + 16 * kb;
                    u32 bh0 = *(const u32*)(w3h + off);
                    u32 bh1 = *(const u32*)(w3h + off + 8);
                    u32 bl0 = *(const u32*)(w3l + off);
                    u32 bl1 = *(const u32*)(w3l + off + 8);
                    #pragma unroll
                    for (int mt = 0; mt < 2; mt++) {
                        mma16816(acc3[mt][nt], a3H[mt][kb], bh0, bh1);
                        mma16816(acc3[mt][nt], a3H[mt][kb], bl0, bl1);
                        mma16816(acc3[mt][nt], a3L[mt][kb], bh0, bh1);
                    }
                }
            }

            // epilogue: relu(acc3 + b3), max over 32 rows, store
            #pragma unroll
            for (int nt = 0; nt < 8; nt++) {
                float2 bb = *(float2*)&b3s[64 * half + 8 * nt + 2 * tidg];
                float me = 0.0f, mo = 0.0f;   // relu lower bound
                #pragma unroll
                for (int mt = 0; mt < 2; mt++) {
                    me = fmaxf(me, fmaxf(acc3[mt][nt][0] + bb.x, acc3[mt][nt][2] + bb.x));
                    mo = fmaxf(mo, fmaxf(acc3[mt][nt][1] + bb.y, acc3[mt][nt][3] + bb.y));
                }
                #pragma unroll
                for (int d = 4; d <= 16; d <<= 1) {
                    me = fmaxf(me, __shfl_xor_sync(0xffffffffu, me, d));
                    mo = fmaxf(mo, __shfl_xor_sync(0xffffffffu, mo, d));
                }
                if (gid == 0) {
                    int o = cent * 128 + 64 * half + 8 * nt + 2 * tidg;
                    out_pts[o] = me;
                    out_pts[o + 1] = mo;
                }
            }
        }
    }
}

// ---------------------------------------------------------------------------
extern "C" void kernel_launch(void* const* d_in, const int* in_sizes, int n_in,
                              void* d_out, int out_size)
{
    const float* xyz    = (const float*)d_in[0];
    const float* points = (const float*)d_in[1];
    const float* W1     = (const float*)d_in[2];
    const float* b1     = (const float*)d_in[3];
    const float* W2     = (const float*)d_in[4];
    const float* b2     = (const float*)d_in[5];
    const float* W3     = (const float*)d_in[6];
    const float* b3     = (const float*)d_in[7];

    float* out = (float*)d_out;
    float* out_xyz = out;
    float* out_pts = out + BB * NPT * 3;
    float* out_idx = out + BB * NPT * 3 + BB * NPT * 128;

    cudaFuncSetAttribute(k_fps_pre1, cudaFuncAttributeMaxDynamicSharedMemorySize, 118784);
    cudaFuncSetAttribute(k_query,    cudaFuncAttributeMaxDynamicSharedMemorySize, 49152);
    cudaFuncSetAttribute(k_mlp_mma,  cudaFuncAttributeMaxDynamicSharedMemorySize, 58368);

    k_prep<<<8, 256>>>(W2, W3);
    k_fps_pre1<<<164, 512, 118784>>>(xyz, points, W1, out_xyz);
    k_query<<<256, 256, 49152>>>(xyz, out_idx);
    k_mlp_mma<<<1024, 128, 58368>>>(W1, b1, b2, b3, out_pts);
}

// round 15
// speedup vs baseline: 3.4663x; 1.0138x over previous
#include <cuda_runtime.h>
#include <cuda_bf16.h>
#include <cstdint>

#define BB 16
#define NN 4096
#define CC 64
#define NPT 1024
#define NSMP 32

typedef unsigned long long u64;
typedef unsigned int u32;

#define WKLD 72   // K-major weight image leading dim (bf16 elems): conflict-free

// ---------------- scratch (device globals; no allocations allowed) ----------
__device__ __align__(16) float g_pre1[BB * NN * CC];   // 16 MB
__device__ float g_new_xyz[BB * NPT * 3];
__device__ int   g_idx[BB * NPT * NSMP];
// K-major padded bf16 weights: W2T hi(0) lo(9216); W3T hi(18432) lo(36864)
__device__ __align__(16) unsigned char g_wimg[55296];

// ---------------- helpers ---------------------------------------------------
__device__ __forceinline__ unsigned redux_max_u32(unsigned v) {
    unsigned r; asm("redux.sync.max.u32 %0, %1, 0xffffffff;" : "=r"(r) : "r"(v)); return r;
}
__device__ __forceinline__ unsigned redux_min_u32(unsigned v) {
    unsigned r; asm("redux.sync.min.u32 %0, %1, 0xffffffff;" : "=r"(r) : "r"(v)); return r;
}
__device__ __forceinline__ u64 pack2(float lo, float hi) {
    u64 r; asm("mov.b64 %0, {%1, %2};" : "=l"(r) : "f"(lo), "f"(hi)); return r;
}
__device__ __forceinline__ void unpack2(u64 v, float& lo, float& hi) {
    asm("mov.b64 {%0, %1}, %2;" : "=f"(lo), "=f"(hi) : "l"(v));
}
__device__ __forceinline__ u64 add2(u64 a, u64 b) {
    u64 r; asm("add.rn.f32x2 %0, %1, %2;" : "=l"(r) : "l"(a), "l"(b)); return r;
}
__device__ __forceinline__ u64 mul2(u64 a, u64 b) {
    u64 r; asm("mul.rn.f32x2 %0, %1, %2;" : "=l"(r) : "l"(a), "l"(b)); return r;
}
// packed bf16x2: first arg -> upper 16 bits, second -> lower
__device__ __forceinline__ u32 cvt_bf16x2(float hi_src, float lo_src) {
    u32 r; asm("cvt.rn.satfinite.bf16x2.f32 %0, %1, %2;" : "=r"(r) : "f"(hi_src), "f"(lo_src)); return r;
}
// mma.m16n8k16 row.col bf16 -> f32, D += A*B
__device__ __forceinline__ void mma16816(float* c, const u32* a, u32 b0, u32 b1) {
    asm volatile(
        "mma.sync.aligned.m16n8k16.row.col.f32.bf16.bf16.f32 "
        "{%0,%1,%2,%3}, {%4,%5,%6,%7}, {%8,%9}, {%0,%1,%2,%3};"
        : "+f"(c[0]), "+f"(c[1]), "+f"(c[2]), "+f"(c[3])
        : "r"(a[0]), "r"(a[1]), "r"(a[2]), "r"(a[3]), "r"(b0), "r"(b1));
}
__device__ __forceinline__ void ldm4(u32& r0, u32& r1, u32& r2, u32& r3, u32 saddr) {
    asm volatile("ldmatrix.sync.aligned.m8n8.x4.shared.b16 {%0,%1,%2,%3}, [%4];"
        : "=r"(r0), "=r"(r1), "=r"(r2), "=r"(r3) : "r"(saddr));
}
__device__ __forceinline__ u32 smem_u32(const void* p) {
    return (u32)__cvta_generic_to_shared(p);
}
__device__ __forceinline__ float low_of(u32 hi)  { return __uint_as_float(hi << 16); }
__device__ __forceinline__ float high_of(u32 hi) { return __uint_as_float(hi & 0xffff0000u); }

// ---------------------------------------------------------------------------
// K0: prep — W2^T / W3^T (K-major rows, padded WKLD) split into bf16 hi/lo
// ---------------------------------------------------------------------------
extern "C" __global__ void k_prep(const float* __restrict__ W2, const float* __restrict__ W3)
{
    int tid = blockIdx.x * blockDim.x + threadIdx.x;
    __nv_bfloat16* w2h = (__nv_bfloat16*)(g_wimg);
    __nv_bfloat16* w2l = (__nv_bfloat16*)(g_wimg + 9216);
    __nv_bfloat16* w3h = (__nv_bfloat16*)(g_wimg + 18432);
    __nv_bfloat16* w3l = (__nv_bfloat16*)(g_wimg + 36864);
    for (int e = tid; e < 64 * 64; e += gridDim.x * blockDim.x) {
        int k = e >> 6, n = e & 63;
        float v = W2[e];                       // W2[k][n]
        __nv_bfloat16 hb = __float2bfloat16(v);
        float hf = __bfloat162float(hb);
        w2h[n * WKLD + k] = hb;
        w2l[n * WKLD + k] = __float2bfloat16(v - hf);
    }
    for (int e = tid; e < 64 * 128; e += gridDim.x * blockDim.x) {
        int k = e >> 7, n = e & 127;
        float v = W3[e];                       // W3[k][n]
        __nv_bfloat16 hb = __float2bfloat16(v);
        float hf = __bfloat162float(hb);
        w3h[n * WKLD + k] = hb;
        w3l[n * WKLD + k] = __float2bfloat16(v - hf);
    }
}

// ---------------------------------------------------------------------------
// K1: FPS (blocks [0,16)) + pre1 (rest)
// scp float4 array: one LDS.128 per centroid fetch (was 3 LDS.32)
// smem: scp[4096]f4 (0) | sx(16384f) sy(20480f) sz(24576f) | spair(28672f)
//       sfps(28736f..) ; total 119040 B -> 1 block/SM
// ---------------------------------------------------------------------------
extern "C" __global__ void __launch_bounds__(512)
k_fps_pre1(const float* __restrict__ xyz, const float* __restrict__ points,
           const float* __restrict__ W1, float* __restrict__ out_xyz)
{
    extern __shared__ float sm[];
    int t = threadIdx.x;

    if (blockIdx.x < BB) {
        int b = blockIdx.x;
        float4* scp = (float4*)sm;
        float* sx = sm + 16384;
        float* sy = sm + 20480;
        float* sz = sm + 24576;
        uint2* spair = (uint2*)(sm + 28672);
        int*   sfps  = (int*)(sm + 28736);

        const float* xb = xyz + (size_t)b * NN * 3;
        for (int i = t; i < NN * 3; i += 512) {
            int n = i / 3, c = i - n * 3;
            float v = xb[i];
            ((c == 0) ? sx : (c == 1) ? sy : sz)[n] = v;
        }
        for (int i = t; i < NN; i += 512)
            scp[i] = make_float4(xb[3 * i], xb[3 * i + 1], xb[3 * i + 2], 0.0f);
        __syncthreads();

        float dd[8];
        u64 PX[4], PY[4], PZ[4];
        #pragma unroll
        for (int a = 0; a < 4; a++) {
            int p0 = t + (2 * a) * 512, p1 = t + (2 * a + 1) * 512;
            PX[a] = pack2(sx[p0], sx[p1]);
            PY[a] = pack2(sy[p0], sy[p1]);
            PZ[a] = pack2(sz[p0], sz[p1]);
            dd[2 * a] = 1e10f; dd[2 * a + 1] = 1e10f;
        }

        int warp = t >> 5, lane = t & 31;
        int far = 0;
        float4 cc = scp[0];

        for (int s = 0; s < NPT; s++) {
            if (t == 0) sfps[s] = far;

            u64 ncx = pack2(-cc.x, -cc.x);
            u64 ncy = pack2(-cc.y, -cc.y);
            u64 ncz = pack2(-cc.z, -cc.z);

            unsigned lb = 0; int li = t;
            #pragma unroll
            for (int a = 0; a < 4; a++) {
                u64 dx = add2(PX[a], ncx);
                u64 dy = add2(PY[a], ncy);
                u64 dz = add2(PZ[a], ncz);
                u64 d2 = add2(add2(mul2(dx, dx), mul2(dy, dy)), mul2(dz, dz));
                float dlo, dhi;
                unpack2(d2, dlo, dhi);
                dd[2 * a]     = fminf(dd[2 * a], dlo);
                dd[2 * a + 1] = fminf(dd[2 * a + 1], dhi);
                unsigned blo = __float_as_uint(dd[2 * a]);
                unsigned bhi = __float_as_uint(dd[2 * a + 1]);
                if (a == 0) { lb = blo; li = t; }
                else if (blo > lb) { lb = blo; li = t + (2 * a) * 512; }
                if (bhi > lb) { lb = bhi; li = t + (2 * a + 1) * 512; }
            }
            unsigned wmax = redux_max_u32(lb);
            unsigned cand = (lb == wmax) ? (unsigned)li : 0xffffffffu;
            unsigned wbesti = redux_min_u32(cand);
            if (lane == 0) spair[(s & 1) * 16 + warp] = make_uint2(wmax, wbesti);
            __syncthreads();
            uint2 pr = spair[(s & 1) * 16 + (lane & 15)];
            unsigned gmax = redux_max_u32(pr.x);
            unsigned c2 = (pr.x == gmax) ? pr.y : 0xffffffffu;
            far = (int)redux_min_u32(c2);
            cc = scp[far];
        }
        __syncthreads();

        #pragma unroll
        for (int hh = 0; hh < 2; hh++) {
            int sc = t + hh * 512;
            int fi = sfps[sc];
            float4 v = scp[fi];
            int o = (b * NPT + sc) * 3;
            g_new_xyz[o] = v.x; g_new_xyz[o + 1] = v.y; g_new_xyz[o + 2] = v.z;
            out_xyz[o] = v.x; out_xyz[o + 1] = v.y; out_xyz[o + 2] = v.z;
        }
    } else {
        float* W1s = sm;
        for (int i = t; i < 67 * 64; i += 512) W1s[i] = W1[i];
        __syncthreads();
        int nb = gridDim.x - BB;
        const int total = BB * NN * CC;
        for (int e = (blockIdx.x - BB) * 512 + t; e < total; e += nb * 512) {
            int r = e >> 6;
            int d = e & 63;
            const float* xr = xyz + (size_t)r * 3;
            float acc = fmaf(xr[2], W1s[2 * 64 + d],
                        fmaf(xr[1], W1s[1 * 64 + d], xr[0] * W1s[d]));
            const float* pr = points + (size_t)r * 64;
            #pragma unroll 8
            for (int c = 0; c < 64; c++)
                acc = fmaf(pr[c], W1s[(3 + c) * 64 + d], acc);
            g_pre1[e] = acc;
        }
    }
}

// ---------------------------------------------------------------------------
// K2: query_ball — 128 blocks x 512 thr (staging amortized 2x vs R14)
// ---------------------------------------------------------------------------
extern "C" __global__ void __launch_bounds__(512)
k_query(const float* __restrict__ xyz, float* __restrict__ out_idx)
{
    extern __shared__ float sm[];
    float* sx = sm;
    float* sy = sm + NN;
    float* sz = sm + 2 * NN;
    int b = blockIdx.x >> 3;
    int sub = blockIdx.x & 7;

    const float* xb = xyz + (size_t)b * NN * 3;
    for (int i = threadIdx.x; i < NN * 3; i += 512) {
        int n = i / 3, c = i - n * 3;
        ((c == 0) ? sx : (c == 1) ? sy : sz)[n] = xb[i];
    }
    __syncthreads();

    int warp = threadIdx.x >> 5, lane = threadIdx.x & 31;
    const float R2 = 0.04f;

    for (int q = 0; q < 8; q++) {
        int s = sub * 128 + warp * 8 + q;
        int cb = b * NPT + s;
        float cx = g_new_xyz[cb * 3], cy = g_new_xyz[cb * 3 + 1], cz = g_new_xyz[cb * 3 + 2];
        int base = cb * NSMP;
        int cnt = 0, first = 0;
        for (int ch = 0; ch < NN / 32; ch++) {
            int p = ch * 32 + lane;
            float dx = __fadd_rn(sx[p], -cx);
            float dy = __fadd_rn(sy[p], -cy);
            float dz = __fadd_rn(sz[p], -cz);
            float d = __fadd_rn(__fadd_rn(__fmul_rn(dx, dx), __fmul_rn(dy, dy)),
                                __fmul_rn(dz, dz));
            bool ok = (d <= R2);
            unsigned m = __ballot_sync(0xffffffffu, ok);
            if (m) {
                if (cnt == 0) first = ch * 32 + __ffs(m) - 1;
                int pos = cnt + __popc(m & ((1u << lane) - 1u));
                if (ok && pos < NSMP) {
                    g_idx[base + pos] = p;
                    out_idx[base + pos] = (float)p;
                }
                cnt += __popc(m);
                if (cnt >= NSMP) break;
            }
        }
        if (cnt < NSMP) {
            int slot = cnt + lane;
            if (slot < NSMP) {
                g_idx[base + slot] = first;
                out_idx[base + slot] = (float)first;
            }
        }
    }
}

// ---------------------------------------------------------------------------
// K3: raw mma.m16n8k16 MLP, fragment-chained, ldmatrix.x4 B loads.
// __launch_bounds__(128,3): <=170 regs -> 3 blocks/SM (reg-file limited)
// ---------------------------------------------------------------------------
extern "C" __global__ void __launch_bounds__(128, 3)
k_mlp_mma(const float* __restrict__ W1, const float* __restrict__ b1,
          const float* __restrict__ b2, const float* __restrict__ b3,
          float* __restrict__ out_pts)
{
    extern __shared__ __align__(16) char smc[];
    int tid = threadIdx.x;
    int wid = tid >> 5, lane = tid & 31;
    int gid = lane >> 2, tidg = lane & 3;

    float* b2s  = (float*)(smc + 55296);
    float* b3s  = (float*)(smc + 55552);
    float* W1x  = (float*)(smc + 56064);
    float* b1s  = (float*)(smc + 56832);
    float* coffs = (float*)(smc + 57088);

    // ---- stage weights + small tensors ----
    {
        const float4* src = (const float4*)g_wimg;
        float4* dst = (float4*)smc;
        for (int i = tid; i < 3456; i += 128) dst[i] = src[i];
        if (tid < 64) {
            b2s[tid] = b2[tid];
            b1s[tid] = b1[tid];
            W1x[tid] = W1[tid]; W1x[64 + tid] = W1[64 + tid]; W1x[128 + tid] = W1[128 + tid];
        }
        b3s[tid] = b3[tid];
    }
    __syncthreads();

    // shared-space weight bases + per-lane ldmatrix row offset
    u32 sbase = smem_u32(smc);
    u32 w2h_s = sbase, w2l_s = sbase + 9216;
    u32 w3h_s = sbase + 18432, w3l_s = sbase + 36864;
    int lt = lane >> 3, lr = lane & 7;
    u32 lro = (u32)(((lt >> 1) * 8 + lr) * (WKLD * 2) + (lt & 1) * 16);

    for (int it = 0; it < 4; it++) {
        int cent = (blockIdx.x * 4 + it) * 4 + wid;
        int b = cent >> 10;

        // ---- coff = b1 - new_xyz @ W1[:3] (per warp) ----
        float ccx = g_new_xyz[cent * 3], ccy = g_new_xyz[cent * 3 + 1], ccz = g_new_xyz[cent * 3 + 2];
        float* co = coffs + wid * 64;
        #pragma unroll
        for (int r = 0; r < 2; r++) {
            int d = lane + r * 32;
            co[d] = b1s[d] - (ccx * W1x[d] + ccy * W1x[64 + d] + ccz * W1x[128 + d]);
        }
        __syncwarp();

        // ---- row pointers: sample row j needed by this lane = gid + 8j ----
        int p = g_idx[cent * NSMP + lane];
        const float* rowp[4];
        #pragma unroll
        for (int j = 0; j < 4; j++) {
            int pj = __shfl_sync(0xffffffffu, p, gid + 8 * j);
            rowp[j] = g_pre1 + ((size_t)(b * NN + pj)) * 64;
        }

        // ---- A1 fragments straight from gmem: h1 = relu(pre1 + co), split ----
        u32 a1H[2][4][4], a1L[2][4][4];
        #pragma unroll
        for (int mt = 0; mt < 2; mt++) {
            #pragma unroll
            for (int kb = 0; kb < 4; kb++) {
                int cA = 2 * tidg + 16 * kb;
                float2 coA = *(float2*)&co[cA];
                float2 coB = *(float2*)&co[cA + 8];
                #pragma unroll
                for (int rr = 0; rr < 4; rr++) {
                    const float* rp = rowp[mt * 2 + (rr & 1)];
                    int col = cA + ((rr >> 1) ? 8 : 0);
                    float2 cv = (rr >> 1) ? coB : coA;
                    float2 v = *(const float2*)(rp + col);
                    float h0 = fmaxf(v.x + cv.x, 0.0f);
                    float h1 = fmaxf(v.y + cv.y, 0.0f);
                    u32 hi = cvt_bf16x2(h1, h0);
                    a1H[mt][kb][rr] = hi;
                    a1L[mt][kb][rr] = cvt_bf16x2(h1 - high_of(hi), h0 - low_of(hi));
                }
            }
        }

        // ---- layer 2: acc2[2][8] (32x64), ldmatrix.x4 B loads ----
        float acc2[2][8][4];
        #pragma unroll
        for (int mt = 0; mt < 2; mt++)
            #pragma unroll
            for (int nt = 0; nt < 8; nt++)
                #pragma unroll
                for (int r = 0; r < 4; r++) acc2[mt][nt][r] = 0.0f;

        #pragma unroll
        for (int kb = 0; kb < 4; kb++) {
            #pragma unroll
            for (int ntp = 0; ntp < 8; ntp += 2) {
                u32 off = (u32)(ntp * (8 * WKLD * 2) + kb * 32) + lro;
                u32 bh0, bh1, bh2, bh3, bl0, bl1, bl2, bl3;
                ldm4(bh0, bh1, bh2, bh3, w2h_s + off);
                ldm4(bl0, bl1, bl2, bl3, w2l_s + off);
                #pragma unroll
                for (int mt = 0; mt < 2; mt++) {
                    mma16816(acc2[mt][ntp], a1H[mt][kb], bh0, bh1);
                    mma16816(acc2[mt][ntp], a1H[mt][kb], bl0, bl1);
                    mma16816(acc2[mt][ntp], a1L[mt][kb], bh0, bh1);
                    mma16816(acc2[mt][ntp + 1], a1H[mt][kb], bh2, bh3);
                    mma16816(acc2[mt][ntp + 1], a1H[mt][kb], bl2, bl3);
                    mma16816(acc2[mt][ntp + 1], a1L[mt][kb], bh2, bh3);
                }
            }
        }

        // ---- h2 = relu(acc2 + b2) -> layer3 A fragments (in registers) ----
        u32 a3H[2][4][4], a3L[2][4][4];
        #pragma unroll
        for (int mt = 0; mt < 2; mt++) {
            #pragma unroll
            for (int kb = 0; kb < 4; kb++) {
                #pragma unroll
                for (int half = 0; half < 2; half++) {
                    int nt = 2 * kb + half;
                    float2 bb = *(float2*)&b2s[8 * nt + 2 * tidg];
                    #pragma unroll
                    for (int rp = 0; rp < 2; rp++) {
                        float h0 = fmaxf(acc2[mt][nt][2 * rp]     + bb.x, 0.0f);
                        float h1 = fmaxf(acc2[mt][nt][2 * rp + 1] + bb.y, 0.0f);
                        u32 hi = cvt_bf16x2(h1, h0);
                        int r = half * 2 + rp;
                        a3H[mt][kb][r] = hi;
                        a3L[mt][kb][r] = cvt_bf16x2(h1 - high_of(hi), h0 - low_of(hi));
                    }
                }
            }
        }

        // ---- layer 3 in 2 halves of N=64; epilogue per n-tile ----
        #pragma unroll
        for (int half = 0; half < 2; half++) {
            u32 w3h_b = w3h_s + half * (64 * WKLD * 2);
            u32 w3l_b = w3l_s + half * (64 * WKLD * 2);
            float acc3[2][8][4];
            #pragma unroll
            for (int mt = 0; mt < 2; mt++)
                #pragma unroll
                for (int nt = 0; nt < 8; nt++)
                    #pragma unroll
                    for (int r = 0; r < 4; r++) acc3[mt][nt][r] = 0.0f;

            #pragma unroll
            for (int kb = 0; kb < 4; kb++) {
                #pragma unroll
                for (int ntp = 0; ntp < 8; ntp += 2) {
                    u32 off = (u32)(ntp * (8 * WKLD * 2) + kb * 32) + lro;
                    u32 bh0, bh1, bh2, bh3, bl0, bl1, bl2, bl3;
                    ldm4(bh0, bh1, bh2, bh3, w3h_b + off);
                    ldm4(bl0, bl1, bl2, bl3, w3l_b + off);
                    #pragma unroll
                    for (int mt = 0; mt < 2; mt++) {
                        mma16816(acc3[mt][ntp], a3H[mt][kb], bh0, bh1);
                        mma16816(acc3[mt][ntp], a3H[mt][kb], bl0, bl1);
                        mma16816(acc3[mt][ntp], a3L[mt][kb], bh0, bh1);
                        mma16816(acc3[mt][ntp + 1], a3H[mt][kb], bh2, bh3);
                        mma16816(acc3[mt][ntp + 1], a3H[mt][kb], bl2, bl3);
                        mma16816(acc3[mt][ntp + 1], a3L[mt][kb], bh2, bh3);
                    }
                }
            }

            // epilogue: relu(acc3 + b3), max over 32 rows, store
            #pragma unroll
            for (int nt = 0; nt < 8; nt++) {
                float2 bb = *(float2*)&b3s[64 * half + 8 * nt + 2 * tidg];
                float me = 0.0f, mo = 0.0f;   // relu lower bound
                #pragma unroll
                for (int mt = 0; mt < 2; mt++) {
                    me = fmaxf(me, fmaxf(acc3[mt][nt][0] + bb.x, acc3[mt][nt][2] + bb.x));
                    mo = fmaxf(mo, fmaxf(acc3[mt][nt][1] + bb.y, acc3[mt][nt][3] + bb.y));
                }
                #pragma unroll
                for (int d = 4; d <= 16; d <<= 1) {
                    me = fmaxf(me, __shfl_xor_sync(0xffffffffu, me, d));
                    mo = fmaxf(mo, __shfl_xor_sync(0xffffffffu, mo, d));
                }
                if (gid == 0) {
                    int o = cent * 128 + 64 * half + 8 * nt + 2 * tidg;
                    out_pts[o] = me;
                    out_pts[o + 1] = mo;
                }
            }
        }
    }
}

// ---------------------------------------------------------------------------
extern "C" void kernel_launch(void* const* d_in, const int* in_sizes, int n_in,
                              void* d_out, int out_size)
{
    const float* xyz    = (const float*)d_in[0];
    const float* points = (const float*)d_in[1];
    const float* W1     = (const float*)d_in[2];
    const float* b1     = (const float*)d_in[3];
    const float* W2     = (const float*)d_in[4];
    const float* b2     = (const float*)d_in[5];
    const float* W3     = (const float*)d_in[6];
    const float* b3     = (const float*)d_in[7];

    float* out = (float*)d_out;
    float* out_xyz = out;
    float* out_pts = out + BB * NPT * 3;
    float* out_idx = out + BB * NPT * 3 + BB * NPT * 128;

    cudaFuncSetAttribute(k_fps_pre1, cudaFuncAttributeMaxDynamicSharedMemorySize, 119040);
    cudaFuncSetAttribute(k_query,    cudaFuncAttributeMaxDynamicSharedMemorySize, 49152);
    cudaFuncSetAttribute(k_mlp_mma,  cudaFuncAttributeMaxDynamicSharedMemorySize, 58368);

    k_prep<<<8, 256>>>(W2, W3);
    k_fps_pre1<<<164, 512, 119040>>>(xyz, points, W1, out_xyz);
    k_query<<<128, 512, 49152>>>(xyz, out_idx);
    k_mlp_mma<<<1024, 128, 58368>>>(W1, b1, b2, b3, out_pts);
}